// round 1
// baseline (speedup 1.0000x reference)
#include <cuda_runtime.h>
#include <cuda_bf16.h>
#include <math.h>

#define DIM 1024
#define NH 16
#define HD 64
#define BATCH 4
#define SEQ 1024
#define BS (BATCH*SEQ)          // 4096 rows
#define MLP_HID 4096
#define LN_EPS 1e-5f

// ---------------- scratch (device globals; no allocation) ----------------
__device__ float g_mod[BATCH * 6 * DIM];                 // 24576
__device__ float g_h[BS * DIM];                          // 16 MB (ln1/ln2 out)
__device__ float g_qkv[BS * 3 * DIM];                    // 48 MB
__device__ float g_scores[(long)BATCH * NH * SEQ * SEQ]; // 256 MB
__device__ float g_o[BS * DIM];                          // 16 MB
__device__ float g_tmp[BS * DIM];                        // 16 MB (attn proj / mlp2 out)
__device__ float g_x2[BS * DIM];                         // 16 MB
__device__ float g_mid[BS * MLP_HID];                    // 64 MB

// ---------------- adaLN modulation: mod = c @ w_ada + b_ada ----------------
__global__ void ada_kernel(const float* __restrict__ c,
                           const float* __restrict__ w_ada,
                           const float* __restrict__ b_ada)
{
    int idx = blockIdx.x * blockDim.x + threadIdx.x;   // 4*6144
    if (idx >= BATCH * 6 * DIM) return;
    int j = idx % (6 * DIM);
    int b = idx / (6 * DIM);
    float s = b_ada[j];
    const float* crow = c + b * DIM;
    #pragma unroll 4
    for (int k = 0; k < DIM; k++)
        s += crow[k] * w_ada[k * (6 * DIM) + j];
    g_mod[idx] = s;
}

// ---------------- LayerNorm + modulate ----------------
// out = LN(x)*w * (1+mod[scale_chunk]) + mod[shift_chunk]
__global__ void ln_mod_kernel(const float* __restrict__ x,
                              const float* __restrict__ w,
                              int shift_chunk, int scale_chunk,
                              float* __restrict__ out)
{
    int row = blockIdx.x;              // 0..4095
    int b = row >> 10;
    int t = threadIdx.x;               // 256 threads, 4 cols each
    const float* xr = x + (size_t)row * DIM;
    float4 v = *(const float4*)(xr + t * 4);
    float sum = v.x + v.y + v.z + v.w;
    float sq  = v.x*v.x + v.y*v.y + v.z*v.z + v.w*v.w;

    __shared__ float s1[256], s2[256];
    s1[t] = sum; s2[t] = sq;
    __syncthreads();
    for (int off = 128; off > 0; off >>= 1) {
        if (t < off) { s1[t] += s1[t + off]; s2[t] += s2[t + off]; }
        __syncthreads();
    }
    float mean = s1[0] * (1.0f / DIM);
    float var  = s2[0] * (1.0f / DIM) - mean * mean;
    float rstd = rsqrtf(var + LN_EPS);

    const float* shiftp = g_mod + b * 6 * DIM + shift_chunk * DIM;
    const float* scalep = g_mod + b * 6 * DIM + scale_chunk * DIM;
    float* orow = out + (size_t)row * DIM;
    #pragma unroll
    for (int u = 0; u < 4; u++) {
        int col = t * 4 + u;
        float xv = (u == 0) ? v.x : (u == 1) ? v.y : (u == 2) ? v.z : v.w;
        float y = (xv - mean) * rstd * w[col];
        orow[col] = y * (1.0f + scalep[col]) + shiftp[col];
    }
}

// ---------------- generic SGEMM: C[M,N] = A[M,K] @ B[K,N] (+bias)(+gelu) ----------------
// BM=BN=128, BK=8, 256 threads, 8x8 per-thread microtile.
__global__ void sgemm_kernel(const float* __restrict__ A,
                             const float* __restrict__ B,
                             const float* __restrict__ bias,
                             float* __restrict__ C,
                             int M, int N, int K, int act)
{
    __shared__ float As[8][128];
    __shared__ float Bs[8][128];
    int t = threadIdx.x;
    int bm = blockIdx.y * 128;
    int bn = blockIdx.x * 128;
    int tx = t & 15, ty = t >> 4;

    float acc[8][8];
    #pragma unroll
    for (int i = 0; i < 8; i++)
        #pragma unroll
        for (int j = 0; j < 8; j++) acc[i][j] = 0.f;

    int arow = t >> 1;          // 0..127
    int acol = (t & 1) * 4;     // 0 or 4
    int brow = t >> 5;          // 0..7
    int bcol = (t & 31) * 4;    // 0..124

    const float* Aptr = A + (size_t)(bm + arow) * K + acol;
    const float* Bptr = B + (size_t)brow * N + bn + bcol;

    for (int k0 = 0; k0 < K; k0 += 8) {
        float4 av = *(const float4*)(Aptr + k0);
        float4 bv = *(const float4*)(Bptr + (size_t)k0 * N);
        As[acol + 0][arow] = av.x;
        As[acol + 1][arow] = av.y;
        As[acol + 2][arow] = av.z;
        As[acol + 3][arow] = av.w;
        *(float4*)&Bs[brow][bcol] = bv;
        __syncthreads();

        #pragma unroll
        for (int kk = 0; kk < 8; kk++) {
            float a[8], bb[8];
            *(float4*)(a)     = *(const float4*)&As[kk][ty * 8];
            *(float4*)(a + 4) = *(const float4*)&As[kk][ty * 8 + 4];
            *(float4*)(bb)    = *(const float4*)&Bs[kk][tx * 8];
            *(float4*)(bb + 4)= *(const float4*)&Bs[kk][tx * 8 + 4];
            #pragma unroll
            for (int i = 0; i < 8; i++)
                #pragma unroll
                for (int j = 0; j < 8; j++)
                    acc[i][j] += a[i] * bb[j];
        }
        __syncthreads();
    }

    #pragma unroll
    for (int i = 0; i < 8; i++) {
        int row = bm + ty * 8 + i;
        #pragma unroll
        for (int j = 0; j < 8; j++) {
            int col = bn + tx * 8 + j;
            float v = acc[i][j];
            if (bias) v += bias[col];
            if (act == 1) {
                float u = v;
                v = 0.5f * u * (1.0f + tanhf(0.7978845608028654f *
                        (u + 0.044715f * u * u * u)));
            }
            C[(size_t)row * N + col] = v;
        }
    }
}

// ---------------- RoPE (in-place on q,k planes of g_qkv) ----------------
__global__ void rope_kernel(const float* __restrict__ cosb,
                            const float* __restrict__ sinb)
{
    int idx = blockIdx.x * blockDim.x + threadIdx.x; // B*S*NH*32 = 2M
    if (idx >= BATCH * SEQ * NH * 32) return;
    int i = idx & 31;
    int h = (idx >> 5) & 15;
    int s = (idx >> 9) & 1023;
    int b = idx >> 19;
    float co = cosb[s * 32 + i];
    float si = sinb[s * 32 + i];
    #pragma unroll
    for (int p = 0; p < 2; p++) {
        int base = ((((b * SEQ + s) * 3 + p) * NH) + h) * HD;
        float t1 = g_qkv[base + i];
        float t2 = g_qkv[base + 32 + i];
        g_qkv[base + i]      = t1 * co - t2 * si;
        g_qkv[base + 32 + i] = t2 * co + t1 * si;
    }
}

// ---------------- scores = Q @ K^T * scale ----------------
// grid (S/64, S/64, B*NH), 256 threads, 4x4 microtile
__global__ void qk_kernel()
{
    __shared__ float Qs[64][65];
    __shared__ float Ks[64][65];
    int bh = blockIdx.z;
    int b = bh >> 4, h = bh & 15;
    int scol0 = blockIdx.x * 64;
    int srow0 = blockIdx.y * 64;
    int t = threadIdx.x;

    int r = t >> 2;
    int c0 = (t & 3) * 16;
    const float* qbase = g_qkv + ((((size_t)(b * SEQ + srow0 + r)) * 3 + 0) * NH + h) * HD;
    const float* kbase = g_qkv + ((((size_t)(b * SEQ + scol0 + r)) * 3 + 1) * NH + h) * HD;
    #pragma unroll
    for (int i = 0; i < 4; i++) {
        float4 qv = *(const float4*)(qbase + c0 + i * 4);
        float4 kv = *(const float4*)(kbase + c0 + i * 4);
        Qs[r][c0 + i*4 + 0] = qv.x; Qs[r][c0 + i*4 + 1] = qv.y;
        Qs[r][c0 + i*4 + 2] = qv.z; Qs[r][c0 + i*4 + 3] = qv.w;
        Ks[r][c0 + i*4 + 0] = kv.x; Ks[r][c0 + i*4 + 1] = kv.y;
        Ks[r][c0 + i*4 + 2] = kv.z; Ks[r][c0 + i*4 + 3] = kv.w;
    }
    __syncthreads();

    int tx = t & 15, ty = t >> 4;
    float acc[4][4];
    #pragma unroll
    for (int i = 0; i < 4; i++)
        #pragma unroll
        for (int j = 0; j < 4; j++) acc[i][j] = 0.f;

    #pragma unroll 8
    for (int d = 0; d < 64; d++) {
        float a[4], bb[4];
        #pragma unroll
        for (int i = 0; i < 4; i++) a[i]  = Qs[ty * 4 + i][d];
        #pragma unroll
        for (int j = 0; j < 4; j++) bb[j] = Ks[tx * 4 + j][d];
        #pragma unroll
        for (int i = 0; i < 4; i++)
            #pragma unroll
            for (int j = 0; j < 4; j++)
                acc[i][j] += a[i] * bb[j];
    }

    float* srow = g_scores + ((size_t)bh * SEQ) * SEQ;
    #pragma unroll
    for (int i = 0; i < 4; i++)
        #pragma unroll
        for (int j = 0; j < 4; j++)
            srow[(size_t)(srow0 + ty*4 + i) * SEQ + scol0 + tx*4 + j] = acc[i][j] * 0.125f;
}

// ---------------- softmax over last dim (rows of 1024) ----------------
__global__ void softmax_kernel()
{
    int row = blockIdx.x;                 // 65536 rows
    int t = threadIdx.x;                  // 256
    float* rp = g_scores + (size_t)row * SEQ;
    float4 v = *(const float4*)(rp + t * 4);
    float m = fmaxf(fmaxf(v.x, v.y), fmaxf(v.z, v.w));
    __shared__ float red[256];
    red[t] = m; __syncthreads();
    for (int off = 128; off > 0; off >>= 1) {
        if (t < off) red[t] = fmaxf(red[t], red[t + off]);
        __syncthreads();
    }
    m = red[0];
    __syncthreads();
    v.x = __expf(v.x - m); v.y = __expf(v.y - m);
    v.z = __expf(v.z - m); v.w = __expf(v.w - m);
    red[t] = v.x + v.y + v.z + v.w; __syncthreads();
    for (int off = 128; off > 0; off >>= 1) {
        if (t < off) red[t] += red[t + off];
        __syncthreads();
    }
    float inv = 1.0f / red[0];
    v.x *= inv; v.y *= inv; v.z *= inv; v.w *= inv;
    *(float4*)(rp + t * 4) = v;
}

// ---------------- O = P @ V ----------------
// grid (S/64, B*NH), 256 threads, 4x4 microtile; N=64 full
__global__ void pv_kernel()
{
    __shared__ float Ps[64][33];
    __shared__ float Vs[32][64];
    int bh = blockIdx.y;
    int b = bh >> 4, h = bh & 15;
    int srow0 = blockIdx.x * 64;
    int t = threadIdx.x;
    int tx = t & 15, ty = t >> 4;

    float acc[4][4];
    #pragma unroll
    for (int i = 0; i < 4; i++)
        #pragma unroll
        for (int j = 0; j < 4; j++) acc[i][j] = 0.f;

    for (int kt = 0; kt < SEQ; kt += 32) {
        // P tile 64x32
        {
            int r = t >> 2;
            int c0 = (t & 3) * 8;
            const float* pbase = g_scores + ((size_t)bh * SEQ + srow0 + r) * SEQ + kt + c0;
            #pragma unroll
            for (int i = 0; i < 2; i++) {
                float4 pv = *(const float4*)(pbase + i * 4);
                Ps[r][c0 + i*4 + 0] = pv.x; Ps[r][c0 + i*4 + 1] = pv.y;
                Ps[r][c0 + i*4 + 2] = pv.z; Ps[r][c0 + i*4 + 3] = pv.w;
            }
        }
        // V tile 32x64
        {
            int r = t >> 3;              // 0..31
            int c0 = (t & 7) * 8;
            const float* vbase = g_qkv + ((((size_t)(b * SEQ + kt + r)) * 3 + 2) * NH + h) * HD + c0;
            float4 v0 = *(const float4*)(vbase);
            float4 v1 = *(const float4*)(vbase + 4);
            *(float4*)&Vs[r][c0] = v0;
            *(float4*)&Vs[r][c0 + 4] = v1;
        }
        __syncthreads();

        #pragma unroll 8
        for (int kk = 0; kk < 32; kk++) {
            float a[4], bb[4];
            #pragma unroll
            for (int i = 0; i < 4; i++) a[i]  = Ps[ty * 4 + i][kk];
            #pragma unroll
            for (int j = 0; j < 4; j++) bb[j] = Vs[kk][tx * 4 + j];
            #pragma unroll
            for (int i = 0; i < 4; i++)
                #pragma unroll
                for (int j = 0; j < 4; j++)
                    acc[i][j] += a[i] * bb[j];
        }
        __syncthreads();
    }

    #pragma unroll
    for (int i = 0; i < 4; i++) {
        int s = srow0 + ty * 4 + i;
        #pragma unroll
        for (int j = 0; j < 4; j++) {
            int d = tx * 4 + j;
            g_o[(((size_t)(b * SEQ + s)) * NH + h) * HD + d] = acc[i][j];
        }
    }
}

// ---------------- residual with gate: out = a + gate[chunk] * t ----------------
__global__ void resid_kernel(const float* __restrict__ a,
                             const float* __restrict__ tm,
                             int gate_chunk,
                             float* __restrict__ out)
{
    int idx = blockIdx.x * blockDim.x + threadIdx.x;  // over 1M float4s
    if (idx >= BS * DIM / 4) return;
    int e0 = idx * 4;
    int b = e0 >> 20;
    int col = e0 & 1023;
    const float* gp = g_mod + b * 6 * DIM + gate_chunk * DIM + col;
    float4 av = *(const float4*)(a + e0);
    float4 tv = *(const float4*)(tm + e0);
    float4 o;
    o.x = av.x + gp[0] * tv.x;
    o.y = av.y + gp[1] * tv.y;
    o.z = av.z + gp[2] * tv.z;
    o.w = av.w + gp[3] * tv.w;
    *(float4*)(out + e0) = o;
}

// ---------------- launch ----------------
extern "C" void kernel_launch(void* const* d_in, const int* in_sizes, int n_in,
                              void* d_out, int out_size)
{
    const float* x          = (const float*)d_in[0];
    const float* cosb       = (const float*)d_in[1];
    const float* sinb       = (const float*)d_in[2];
    const float* c          = (const float*)d_in[3];
    const float* w_ln1      = (const float*)d_in[4];
    const float* w_ln2      = (const float*)d_in[5];
    const float* w_qkv      = (const float*)d_in[6];
    const float* w_attn_out = (const float*)d_in[7];
    const float* w_mlp1     = (const float*)d_in[8];
    const float* b_mlp1     = (const float*)d_in[9];
    const float* w_mlp2     = (const float*)d_in[10];
    const float* b_mlp2     = (const float*)d_in[11];
    const float* w_ada      = (const float*)d_in[12];
    const float* b_ada      = (const float*)d_in[13];
    float* out = (float*)d_out;

    float *p_mod, *p_h, *p_qkv, *p_o, *p_tmp, *p_x2, *p_mid;
    cudaGetSymbolAddress((void**)&p_mod, g_mod);
    cudaGetSymbolAddress((void**)&p_h,   g_h);
    cudaGetSymbolAddress((void**)&p_qkv, g_qkv);
    cudaGetSymbolAddress((void**)&p_o,   g_o);
    cudaGetSymbolAddress((void**)&p_tmp, g_tmp);
    cudaGetSymbolAddress((void**)&p_x2,  g_x2);
    cudaGetSymbolAddress((void**)&p_mid, g_mid);

    // 1. adaLN modulation
    ada_kernel<<<(BATCH * 6 * DIM + 255) / 256, 256>>>(c, w_ada, b_ada);

    // 2. LN1 + modulate (shift=chunk0, scale=chunk1)
    ln_mod_kernel<<<BS, 256>>>(x, w_ln1, 0, 1, p_h);

    // 3. qkv = h @ w_qkv
    sgemm_kernel<<<dim3(3 * DIM / 128, BS / 128), 256>>>(p_h, w_qkv, nullptr, p_qkv,
                                                         BS, 3 * DIM, DIM, 0);

    // 4. RoPE on q,k
    rope_kernel<<<(BATCH * SEQ * NH * 32 + 255) / 256, 256>>>(cosb, sinb);

    // 5. scores = Q K^T * scale
    qk_kernel<<<dim3(SEQ / 64, SEQ / 64, BATCH * NH), 256>>>();

    // 6. softmax
    softmax_kernel<<<BATCH * NH * SEQ, 256>>>();

    // 7. O = P @ V
    pv_kernel<<<dim3(SEQ / 64, BATCH * NH), 256>>>();

    // 8. attn projection
    sgemm_kernel<<<dim3(DIM / 128, BS / 128), 256>>>(p_o, w_attn_out, nullptr, p_tmp,
                                                     BS, DIM, DIM, 0);

    // 9. x2 = x + gate_msa * proj   (gate_msa = chunk2)
    resid_kernel<<<(BS * DIM / 4 + 255) / 256, 256>>>(x, p_tmp, 2, p_x2);

    // 10. LN2 + modulate (shift=chunk3, scale=chunk4)
    ln_mod_kernel<<<BS, 256>>>(p_x2, w_ln2, 3, 4, p_h);

    // 11. mid = gelu(h @ w_mlp1 + b_mlp1)
    sgemm_kernel<<<dim3(MLP_HID / 128, BS / 128), 256>>>(p_h, w_mlp1, b_mlp1, p_mid,
                                                         BS, MLP_HID, DIM, 1);

    // 12. m = mid @ w_mlp2 + b_mlp2
    sgemm_kernel<<<dim3(DIM / 128, BS / 128), 256>>>(p_mid, w_mlp2, b_mlp2, p_tmp,
                                                     BS, DIM, MLP_HID, 0);

    // 13. out = x2 + gate_mlp * m  (gate_mlp = chunk5)
    resid_kernel<<<(BS * DIM / 4 + 255) / 256, 256>>>(p_x2, p_tmp, 5, out);
}

// round 3
// speedup vs baseline: 2.4325x; 2.4325x over previous
#include <cuda_runtime.h>
#include <cuda_bf16.h>
#include <math.h>
#include <stdint.h>

#define DIM 1024
#define NH 16
#define HD 64
#define BATCH 4
#define SEQ 1024
#define BS (BATCH*SEQ)          // 4096 rows
#define MLP_HID 4096
#define LN_EPS 1e-5f

// ---------------- scratch (device globals; no allocation) ----------------
__device__ float g_mod[BATCH * 6 * DIM];
__device__ float g_h[BS * DIM];
__device__ float g_qkv[BS * 3 * DIM];
__device__ float g_scores[(long)BATCH * NH * SEQ * SEQ];
__device__ float g_o[BS * DIM];
__device__ float g_tmp[BS * DIM];
__device__ float g_x2[BS * DIM];
__device__ float g_mid[BS * MLP_HID];

// ================= helpers =================
__device__ __forceinline__ uint32_t f2tf32(float f) {
    uint32_t r;
    asm("cvt.rna.tf32.f32 %0, %1;" : "=r"(r) : "f"(f));
    return r;
}
__device__ __forceinline__ uint4 cvt4(float4 v) {
    uint4 u;
    u.x = f2tf32(v.x); u.y = f2tf32(v.y);
    u.z = f2tf32(v.z); u.w = f2tf32(v.w);
    return u;
}
// D += A(16x8,tf32,row) * B(8x8,tf32,col)
__device__ __forceinline__ void mma8(float* c, const uint32_t* a, const uint32_t* b) {
    asm volatile(
        "mma.sync.aligned.m16n8k8.row.col.f32.tf32.tf32.f32 "
        "{%0,%1,%2,%3}, {%4,%5,%6,%7}, {%8,%9}, {%0,%1,%2,%3};"
        : "+f"(c[0]), "+f"(c[1]), "+f"(c[2]), "+f"(c[3])
        : "r"(a[0]), "r"(a[1]), "r"(a[2]), "r"(a[3]), "r"(b[0]), "r"(b[1]));
}
__device__ __forceinline__ float gelu_f(float u) {
    float y = 0.7978845608028654f * (u + 0.044715f * u * u * u);
    float e = __expf(2.0f * y);
    return u * (1.0f - __fdividef(1.0f, e + 1.0f));
}

// ============ tf32 mma GEMM: C[M,N] = A[M,K] @ B[K,N] (+bias)(+gelu) ============
// 128x128 CTA tile, BK=32, 256 threads = 8 warps (2M x 4N), warp tile 64x32.
#define PADA 36
#define PADB 136

__global__ void __launch_bounds__(256)
tgemm_kernel(const float* __restrict__ A,
             const float* __restrict__ B,
             const float* __restrict__ bias,
             float* __restrict__ C,
             int M, int N, int K, int act)
{
    __shared__ float As[128 * PADA];
    __shared__ float Bs[32 * PADB];
    const int t = threadIdx.x, lane = t & 31, wid = t >> 5;
    const int warpM = wid >> 2, warpN = wid & 3;
    const int bm = blockIdx.y * 128, bn = blockIdx.x * 128;
    const int gid = lane >> 2, tig = lane & 3;

    float acc[4][4][4];
    #pragma unroll
    for (int i = 0; i < 4; i++)
        #pragma unroll
        for (int j = 0; j < 4; j++)
            #pragma unroll
            for (int q = 0; q < 4; q++) acc[i][j][q] = 0.f;

    const int NC = K >> 5;
    float4 ra[4], rb[4];

    // ---- prologue: load tile 0 ----
    #pragma unroll
    for (int i = 0; i < 4; i++) {
        int e = (i * 256 + t) * 4;
        int m = e >> 5, k = e & 31;
        ra[i] = *(const float4*)(A + (size_t)(bm + m) * K + k);
        int bk = e >> 7, n = e & 127;
        rb[i] = *(const float4*)(B + (size_t)bk * N + bn + n);
    }
    #pragma unroll
    for (int i = 0; i < 4; i++) {
        int e = (i * 256 + t) * 4;
        int m = e >> 5, k = e & 31;
        *(uint4*)&As[m * PADA + k] = cvt4(ra[i]);
        int bk = e >> 7, n = e & 127;
        *(uint4*)&Bs[bk * PADB + n] = cvt4(rb[i]);
    }
    __syncthreads();

    for (int kc = 0; kc < NC; kc++) {
        // prefetch next tile into registers
        if (kc + 1 < NC) {
            #pragma unroll
            for (int i = 0; i < 4; i++) {
                int e = (i * 256 + t) * 4;
                int m = e >> 5, k = e & 31;
                ra[i] = *(const float4*)(A + (size_t)(bm + m) * K + (kc + 1) * 32 + k);
                int bk = e >> 7, n = e & 127;
                rb[i] = *(const float4*)(B + (size_t)((kc + 1) * 32 + bk) * N + bn + n);
            }
        }
        // compute current tile
        #pragma unroll
        for (int ks = 0; ks < 4; ks++) {
            uint32_t af[4][4], bf[4][2];
            const int k = ks * 8 + tig;
            #pragma unroll
            for (int mi = 0; mi < 4; mi++) {
                int m = warpM * 64 + mi * 16 + gid;
                af[mi][0] = __float_as_uint(As[m * PADA + k]);
                af[mi][1] = __float_as_uint(As[(m + 8) * PADA + k]);
                af[mi][2] = __float_as_uint(As[m * PADA + k + 4]);
                af[mi][3] = __float_as_uint(As[(m + 8) * PADA + k + 4]);
            }
            #pragma unroll
            for (int ni = 0; ni < 4; ni++) {
                int n = warpN * 32 + ni * 8 + gid;
                bf[ni][0] = __float_as_uint(Bs[k * PADB + n]);
                bf[ni][1] = __float_as_uint(Bs[(k + 4) * PADB + n]);
            }
            #pragma unroll
            for (int mi = 0; mi < 4; mi++)
                #pragma unroll
                for (int ni = 0; ni < 4; ni++)
                    mma8(acc[mi][ni], af[mi], bf[ni]);
        }
        if (kc + 1 < NC) {
            __syncthreads();
            #pragma unroll
            for (int i = 0; i < 4; i++) {
                int e = (i * 256 + t) * 4;
                int m = e >> 5, k = e & 31;
                *(uint4*)&As[m * PADA + k] = cvt4(ra[i]);
                int bk = e >> 7, n = e & 127;
                *(uint4*)&Bs[bk * PADB + n] = cvt4(rb[i]);
            }
            __syncthreads();
        }
    }

    // ---- epilogue ----
    #pragma unroll
    for (int mi = 0; mi < 4; mi++) {
        #pragma unroll
        for (int ni = 0; ni < 4; ni++) {
            int r0 = bm + warpM * 64 + mi * 16 + gid;
            int c0 = bn + warpN * 32 + ni * 8 + tig * 2;
            float v0 = acc[mi][ni][0], v1 = acc[mi][ni][1];
            float v2 = acc[mi][ni][2], v3 = acc[mi][ni][3];
            if (bias) {
                float b0 = bias[c0], b1 = bias[c0 + 1];
                v0 += b0; v1 += b1; v2 += b0; v3 += b1;
            }
            if (act) {
                v0 = gelu_f(v0); v1 = gelu_f(v1);
                v2 = gelu_f(v2); v3 = gelu_f(v3);
            }
            *(float2*)(C + (size_t)r0 * N + c0)       = make_float2(v0, v1);
            *(float2*)(C + (size_t)(r0 + 8) * N + c0) = make_float2(v2, v3);
        }
    }
}

// ============ scores = Q @ K^T * scale  (tf32 mma) ============
// tile 64(srow) x 64(scol) per CTA, 8 warps (2x4), warp tile 32x16.
#define QPAD 68
__global__ void __launch_bounds__(256)
qk_kernel()
{
    __shared__ float Qs[64 * QPAD];
    __shared__ float Ks[64 * QPAD];
    const int t = threadIdx.x, lane = t & 31, wid = t >> 5;
    const int warpM = wid >> 2, warpN = wid & 3;
    const int gid = lane >> 2, tig = lane & 3;
    const int bh = blockIdx.z, b = bh >> 4, h = bh & 15;
    const int scol0 = blockIdx.x * 64, srow0 = blockIdx.y * 64;

    #pragma unroll
    for (int i = 0; i < 4; i++) {
        int e = (i * 256 + t) * 4;
        int r = e >> 6, c = e & 63;
        float4 qv = *(const float4*)(g_qkv + ((size_t)(b * SEQ + srow0 + r) * 3) * 1024 + h * 64 + c);
        *(uint4*)&Qs[r * QPAD + c] = cvt4(qv);
        float4 kv = *(const float4*)(g_qkv + ((size_t)(b * SEQ + scol0 + r) * 3 + 1) * 1024 + h * 64 + c);
        *(uint4*)&Ks[r * QPAD + c] = cvt4(kv);
    }
    __syncthreads();

    float acc[2][2][4];
    #pragma unroll
    for (int i = 0; i < 2; i++)
        #pragma unroll
        for (int j = 0; j < 2; j++)
            #pragma unroll
            for (int q = 0; q < 4; q++) acc[i][j][q] = 0.f;

    #pragma unroll
    for (int ks = 0; ks < 8; ks++) {
        const int k = ks * 8 + tig;
        uint32_t af[2][4], bf[2][2];
        #pragma unroll
        for (int mi = 0; mi < 2; mi++) {
            int m = warpM * 32 + mi * 16 + gid;
            af[mi][0] = __float_as_uint(Qs[m * QPAD + k]);
            af[mi][1] = __float_as_uint(Qs[(m + 8) * QPAD + k]);
            af[mi][2] = __float_as_uint(Qs[m * QPAD + k + 4]);
            af[mi][3] = __float_as_uint(Qs[(m + 8) * QPAD + k + 4]);
        }
        #pragma unroll
        for (int ni = 0; ni < 2; ni++) {
            int n = warpN * 16 + ni * 8 + gid;
            bf[ni][0] = __float_as_uint(Ks[n * QPAD + k]);
            bf[ni][1] = __float_as_uint(Ks[n * QPAD + k + 4]);
        }
        #pragma unroll
        for (int mi = 0; mi < 2; mi++)
            #pragma unroll
            for (int ni = 0; ni < 2; ni++)
                mma8(acc[mi][ni], af[mi], bf[ni]);
    }

    float* sb = g_scores + (size_t)bh * SEQ * SEQ;
    #pragma unroll
    for (int mi = 0; mi < 2; mi++) {
        #pragma unroll
        for (int ni = 0; ni < 2; ni++) {
            int r0 = srow0 + warpM * 32 + mi * 16 + gid;
            int c0 = scol0 + warpN * 16 + ni * 8 + tig * 2;
            *(float2*)(sb + (size_t)r0 * SEQ + c0) =
                make_float2(acc[mi][ni][0] * 0.125f, acc[mi][ni][1] * 0.125f);
            *(float2*)(sb + (size_t)(r0 + 8) * SEQ + c0) =
                make_float2(acc[mi][ni][2] * 0.125f, acc[mi][ni][3] * 0.125f);
        }
    }
}

// ============ O = P @ V  (tf32 mma) ============
// tile 64(s) x 64(d) per CTA, K loop over SEQ in chunks of 32.
#define PPAD 36
#define VPAD 72
__global__ void __launch_bounds__(256)
pv_kernel()
{
    __shared__ float Ps[64 * PPAD];
    __shared__ float Vs[32 * VPAD];
    const int t = threadIdx.x, lane = t & 31, wid = t >> 5;
    const int warpM = wid >> 2, warpN = wid & 3;
    const int gid = lane >> 2, tig = lane & 3;
    const int bh = blockIdx.y, b = bh >> 4, h = bh & 15;
    const int srow0 = blockIdx.x * 64;

    float acc[2][2][4];
    #pragma unroll
    for (int i = 0; i < 2; i++)
        #pragma unroll
        for (int j = 0; j < 2; j++)
            #pragma unroll
            for (int q = 0; q < 4; q++) acc[i][j][q] = 0.f;

    float4 rp[2], rv[2];
    // prologue
    #pragma unroll
    for (int i = 0; i < 2; i++) {
        int e = (i * 256 + t) * 4;
        int pr = e >> 5, pc = e & 31;
        rp[i] = *(const float4*)(g_scores + ((size_t)bh * SEQ + srow0 + pr) * SEQ + pc);
        int vr = e >> 6, vc = e & 63;
        rv[i] = *(const float4*)(g_qkv + ((size_t)(b * SEQ + vr) * 3 + 2) * 1024 + h * 64 + vc);
    }
    #pragma unroll
    for (int i = 0; i < 2; i++) {
        int e = (i * 256 + t) * 4;
        int pr = e >> 5, pc = e & 31;
        *(uint4*)&Ps[pr * PPAD + pc] = cvt4(rp[i]);
        int vr = e >> 6, vc = e & 63;
        *(uint4*)&Vs[vr * VPAD + vc] = cvt4(rv[i]);
    }
    __syncthreads();

    for (int kt = 0; kt < SEQ; kt += 32) {
        if (kt + 32 < SEQ) {
            #pragma unroll
            for (int i = 0; i < 2; i++) {
                int e = (i * 256 + t) * 4;
                int pr = e >> 5, pc = e & 31;
                rp[i] = *(const float4*)(g_scores + ((size_t)bh * SEQ + srow0 + pr) * SEQ + kt + 32 + pc);
                int vr = e >> 6, vc = e & 63;
                rv[i] = *(const float4*)(g_qkv + ((size_t)(b * SEQ + kt + 32 + vr) * 3 + 2) * 1024 + h * 64 + vc);
            }
        }
        #pragma unroll
        for (int ks = 0; ks < 4; ks++) {
            const int k = ks * 8 + tig;
            uint32_t af[2][4], bf[2][2];
            #pragma unroll
            for (int mi = 0; mi < 2; mi++) {
                int m = warpM * 32 + mi * 16 + gid;
                af[mi][0] = __float_as_uint(Ps[m * PPAD + k]);
                af[mi][1] = __float_as_uint(Ps[(m + 8) * PPAD + k]);
                af[mi][2] = __float_as_uint(Ps[m * PPAD + k + 4]);
                af[mi][3] = __float_as_uint(Ps[(m + 8) * PPAD + k + 4]);
            }
            #pragma unroll
            for (int ni = 0; ni < 2; ni++) {
                int n = warpN * 16 + ni * 8 + gid;
                bf[ni][0] = __float_as_uint(Vs[k * VPAD + n]);
                bf[ni][1] = __float_as_uint(Vs[(k + 4) * VPAD + n]);
            }
            #pragma unroll
            for (int mi = 0; mi < 2; mi++)
                #pragma unroll
                for (int ni = 0; ni < 2; ni++)
                    mma8(acc[mi][ni], af[mi], bf[ni]);
        }
        if (kt + 32 < SEQ) {
            __syncthreads();
            #pragma unroll
            for (int i = 0; i < 2; i++) {
                int e = (i * 256 + t) * 4;
                int pr = e >> 5, pc = e & 31;
                *(uint4*)&Ps[pr * PPAD + pc] = cvt4(rp[i]);
                int vr = e >> 6, vc = e & 63;
                *(uint4*)&Vs[vr * VPAD + vc] = cvt4(rv[i]);
            }
            __syncthreads();
        }
    }

    #pragma unroll
    for (int mi = 0; mi < 2; mi++) {
        #pragma unroll
        for (int ni = 0; ni < 2; ni++) {
            int s0 = srow0 + warpM * 32 + mi * 16 + gid;
            int d0 = warpN * 16 + ni * 8 + tig * 2;
            float* op = g_o + (size_t)(b * SEQ + s0) * 1024 + h * 64 + d0;
            *(float2*)op = make_float2(acc[mi][ni][0], acc[mi][ni][1]);
            *(float2*)(op + 8 * 1024) = make_float2(acc[mi][ni][2], acc[mi][ni][3]);
        }
    }
}

// ---------------- adaLN modulation ----------------
__global__ void ada_kernel(const float* __restrict__ c,
                           const float* __restrict__ w_ada,
                           const float* __restrict__ b_ada)
{
    int idx = blockIdx.x * blockDim.x + threadIdx.x;
    if (idx >= BATCH * 6 * DIM) return;
    int j = idx % (6 * DIM);
    int b = idx / (6 * DIM);
    float s = b_ada[j];
    const float* crow = c + b * DIM;
    #pragma unroll 4
    for (int k = 0; k < DIM; k++)
        s += crow[k] * w_ada[k * (6 * DIM) + j];
    g_mod[idx] = s;
}

// ---------------- LayerNorm + modulate ----------------
__global__ void ln_mod_kernel(const float* __restrict__ x,
                              const float* __restrict__ w,
                              int shift_chunk, int scale_chunk,
                              float* __restrict__ out)
{
    int row = blockIdx.x;
    int b = row >> 10;
    int t = threadIdx.x;
    const float* xr = x + (size_t)row * DIM;
    float4 v = *(const float4*)(xr + t * 4);
    float sum = v.x + v.y + v.z + v.w;
    float sq  = v.x*v.x + v.y*v.y + v.z*v.z + v.w*v.w;

    __shared__ float s1[256], s2[256];
    s1[t] = sum; s2[t] = sq;
    __syncthreads();
    for (int off = 128; off > 0; off >>= 1) {
        if (t < off) { s1[t] += s1[t + off]; s2[t] += s2[t + off]; }
        __syncthreads();
    }
    float mean = s1[0] * (1.0f / DIM);
    float var  = s2[0] * (1.0f / DIM) - mean * mean;
    float rstd = rsqrtf(var + LN_EPS);

    const float* shiftp = g_mod + b * 6 * DIM + shift_chunk * DIM;
    const float* scalep = g_mod + b * 6 * DIM + scale_chunk * DIM;
    float* orow = out + (size_t)row * DIM;
    #pragma unroll
    for (int u = 0; u < 4; u++) {
        int col = t * 4 + u;
        float xv = (u == 0) ? v.x : (u == 1) ? v.y : (u == 2) ? v.z : v.w;
        float y = (xv - mean) * rstd * w[col];
        orow[col] = y * (1.0f + scalep[col]) + shiftp[col];
    }
}

// ---------------- RoPE ----------------
__global__ void rope_kernel(const float* __restrict__ cosb,
                            const float* __restrict__ sinb)
{
    int idx = blockIdx.x * blockDim.x + threadIdx.x;
    if (idx >= BATCH * SEQ * NH * 32) return;
    int i = idx & 31;
    int h = (idx >> 5) & 15;
    int s = (idx >> 9) & 1023;
    int b = idx >> 19;
    float co = cosb[s * 32 + i];
    float si = sinb[s * 32 + i];
    #pragma unroll
    for (int p = 0; p < 2; p++) {
        int base = ((((b * SEQ + s) * 3 + p) * NH) + h) * HD;
        float t1 = g_qkv[base + i];
        float t2 = g_qkv[base + 32 + i];
        g_qkv[base + i]      = t1 * co - t2 * si;
        g_qkv[base + 32 + i] = t2 * co + t1 * si;
    }
}

// ---------------- softmax ----------------
__global__ void softmax_kernel()
{
    int row = blockIdx.x;
    int t = threadIdx.x;
    float* rp = g_scores + (size_t)row * SEQ;
    float4 v = *(const float4*)(rp + t * 4);
    float m = fmaxf(fmaxf(v.x, v.y), fmaxf(v.z, v.w));
    __shared__ float red[256];
    red[t] = m; __syncthreads();
    for (int off = 128; off > 0; off >>= 1) {
        if (t < off) red[t] = fmaxf(red[t], red[t + off]);
        __syncthreads();
    }
    m = red[0];
    __syncthreads();
    v.x = __expf(v.x - m); v.y = __expf(v.y - m);
    v.z = __expf(v.z - m); v.w = __expf(v.w - m);
    red[t] = v.x + v.y + v.z + v.w; __syncthreads();
    for (int off = 128; off > 0; off >>= 1) {
        if (t < off) red[t] += red[t + off];
        __syncthreads();
    }
    float inv = 1.0f / red[0];
    v.x *= inv; v.y *= inv; v.z *= inv; v.w *= inv;
    *(float4*)(rp + t * 4) = v;
}

// ---------------- residual with gate ----------------
__global__ void resid_kernel(const float* __restrict__ a,
                             const float* __restrict__ tm,
                             int gate_chunk,
                             float* __restrict__ out)
{
    int idx = blockIdx.x * blockDim.x + threadIdx.x;
    if (idx >= BS * DIM / 4) return;
    int e0 = idx * 4;
    int b = e0 >> 20;
    int col = e0 & 1023;
    const float* gp = g_mod + b * 6 * DIM + gate_chunk * DIM + col;
    float4 av = *(const float4*)(a + e0);
    float4 tv = *(const float4*)(tm + e0);
    float4 o;
    o.x = av.x + gp[0] * tv.x;
    o.y = av.y + gp[1] * tv.y;
    o.z = av.z + gp[2] * tv.z;
    o.w = av.w + gp[3] * tv.w;
    *(float4*)(out + e0) = o;
}

// ---------------- launch ----------------
extern "C" void kernel_launch(void* const* d_in, const int* in_sizes, int n_in,
                              void* d_out, int out_size)
{
    const float* x          = (const float*)d_in[0];
    const float* cosb       = (const float*)d_in[1];
    const float* sinb       = (const float*)d_in[2];
    const float* c          = (const float*)d_in[3];
    const float* w_ln1      = (const float*)d_in[4];
    const float* w_ln2      = (const float*)d_in[5];
    const float* w_qkv      = (const float*)d_in[6];
    const float* w_attn_out = (const float*)d_in[7];
    const float* w_mlp1     = (const float*)d_in[8];
    const float* b_mlp1     = (const float*)d_in[9];
    const float* w_mlp2     = (const float*)d_in[10];
    const float* b_mlp2     = (const float*)d_in[11];
    const float* w_ada      = (const float*)d_in[12];
    const float* b_ada      = (const float*)d_in[13];
    float* out = (float*)d_out;

    float *p_h, *p_qkv, *p_o, *p_tmp, *p_x2, *p_mid;
    cudaGetSymbolAddress((void**)&p_h,   g_h);
    cudaGetSymbolAddress((void**)&p_qkv, g_qkv);
    cudaGetSymbolAddress((void**)&p_o,   g_o);
    cudaGetSymbolAddress((void**)&p_tmp, g_tmp);
    cudaGetSymbolAddress((void**)&p_x2,  g_x2);
    cudaGetSymbolAddress((void**)&p_mid, g_mid);

    // 1. adaLN modulation
    ada_kernel<<<(BATCH * 6 * DIM + 255) / 256, 256>>>(c, w_ada, b_ada);

    // 2. LN1 + modulate
    ln_mod_kernel<<<BS, 256>>>(x, w_ln1, 0, 1, p_h);

    // 3. qkv = h @ w_qkv   (tf32 mma)
    tgemm_kernel<<<dim3(3 * DIM / 128, BS / 128), 256>>>(
        p_h, w_qkv, nullptr, p_qkv, BS, 3 * DIM, DIM, 0);

    // 4. RoPE
    rope_kernel<<<(BATCH * SEQ * NH * 32 + 255) / 256, 256>>>(cosb, sinb);

    // 5. scores = Q K^T * scale (tf32 mma)
    qk_kernel<<<dim3(SEQ / 64, SEQ / 64, BATCH * NH), 256>>>();

    // 6. softmax
    softmax_kernel<<<BATCH * NH * SEQ, 256>>>();

    // 7. O = P @ V (tf32 mma)
    pv_kernel<<<dim3(SEQ / 64, BATCH * NH), 256>>>();

    // 8. attn projection (tf32 mma)
    tgemm_kernel<<<dim3(DIM / 128, BS / 128), 256>>>(
        p_o, w_attn_out, nullptr, p_tmp, BS, DIM, DIM, 0);

    // 9. x2 = x + gate_msa * proj
    resid_kernel<<<(BS * DIM / 4 + 255) / 256, 256>>>(x, p_tmp, 2, p_x2);

    // 10. LN2 + modulate
    ln_mod_kernel<<<BS, 256>>>(p_x2, w_ln2, 3, 4, p_h);

    // 11. mid = gelu(h @ w_mlp1 + b_mlp1)  (tf32 mma)
    tgemm_kernel<<<dim3(MLP_HID / 128, BS / 128), 256>>>(
        p_h, w_mlp1, b_mlp1, p_mid, BS, MLP_HID, DIM, 1);

    // 12. m = mid @ w_mlp2 + b_mlp2  (tf32 mma)
    tgemm_kernel<<<dim3(DIM / 128, BS / 128), 256>>>(
        p_mid, w_mlp2, b_mlp2, p_tmp, BS, DIM, MLP_HID, 0);

    // 13. out = x2 + gate_mlp * m
    resid_kernel<<<(BS * DIM / 4 + 255) / 256, 256>>>(p_x2, p_tmp, 5, out);
}

// round 4
// speedup vs baseline: 2.7155x; 1.1163x over previous
#include <cuda_runtime.h>
#include <cuda_bf16.h>
#include <math.h>
#include <stdint.h>

#define DIM 1024
#define NH 16
#define HD 64
#define BATCH 4
#define SEQ 1024
#define BS (BATCH*SEQ)
#define MLP_HID 4096
#define LN_EPS 1e-5f

// ---------------- scratch ----------------
__device__ float g_mod[BATCH * 6 * DIM];
__device__ float g_h[BS * DIM];
__device__ float g_qkv[BS * 3 * DIM];
__device__ float g_o[BS * DIM];
__device__ float g_tmp[BS * DIM];
__device__ float g_x2[BS * DIM];
__device__ float g_mid[BS * MLP_HID];

// ================= helpers =================
__device__ __forceinline__ uint32_t f2tf32(float f) {
    uint32_t r;
    asm("cvt.rna.tf32.f32 %0, %1;" : "=r"(r) : "f"(f));
    return r;
}
__device__ __forceinline__ uint4 cvt4(float4 v) {
    uint4 u;
    u.x = f2tf32(v.x); u.y = f2tf32(v.y);
    u.z = f2tf32(v.z); u.w = f2tf32(v.w);
    return u;
}
__device__ __forceinline__ void mma8(float* c, const uint32_t* a, const uint32_t* b) {
    asm volatile(
        "mma.sync.aligned.m16n8k8.row.col.f32.tf32.tf32.f32 "
        "{%0,%1,%2,%3}, {%4,%5,%6,%7}, {%8,%9}, {%0,%1,%2,%3};"
        : "+f"(c[0]), "+f"(c[1]), "+f"(c[2]), "+f"(c[3])
        : "r"(a[0]), "r"(a[1]), "r"(a[2]), "r"(a[3]), "r"(b[0]), "r"(b[1]));
}
__device__ __forceinline__ float gelu_f(float u) {
    float y = 0.7978845608028654f * (u + 0.044715f * u * u * u);
    float e = __expf(2.0f * y);
    return u * (1.0f - __fdividef(1.0f, e + 1.0f));
}

// ============ tf32 mma GEMM (+bias)(+gelu)(+gated residual) ============
#define PADA 36
#define PADB 136

__global__ void __launch_bounds__(256)
tgemm_kernel(const float* __restrict__ A,
             const float* __restrict__ B,
             const float* __restrict__ bias,
             const float* __restrict__ resid,   // if non-null: C = resid + gate*C
             float* __restrict__ C,
             int M, int N, int K, int act, int gate_chunk)
{
    __shared__ float As[128 * PADA];
    __shared__ float Bs[32 * PADB];
    const int t = threadIdx.x, lane = t & 31, wid = t >> 5;
    const int warpM = wid >> 2, warpN = wid & 3;
    const int bm = blockIdx.y * 128, bn = blockIdx.x * 128;
    const int gid = lane >> 2, tig = lane & 3;

    float acc[4][4][4];
    #pragma unroll
    for (int i = 0; i < 4; i++)
        #pragma unroll
        for (int j = 0; j < 4; j++)
            #pragma unroll
            for (int q = 0; q < 4; q++) acc[i][j][q] = 0.f;

    const int NC = K >> 5;
    float4 ra[4], rb[4];

    #pragma unroll
    for (int i = 0; i < 4; i++) {
        int e = (i * 256 + t) * 4;
        int m = e >> 5, k = e & 31;
        ra[i] = *(const float4*)(A + (size_t)(bm + m) * K + k);
        int bk = e >> 7, n = e & 127;
        rb[i] = *(const float4*)(B + (size_t)bk * N + bn + n);
    }
    #pragma unroll
    for (int i = 0; i < 4; i++) {
        int e = (i * 256 + t) * 4;
        int m = e >> 5, k = e & 31;
        *(uint4*)&As[m * PADA + k] = cvt4(ra[i]);
        int bk = e >> 7, n = e & 127;
        *(uint4*)&Bs[bk * PADB + n] = cvt4(rb[i]);
    }
    __syncthreads();

    for (int kc = 0; kc < NC; kc++) {
        if (kc + 1 < NC) {
            #pragma unroll
            for (int i = 0; i < 4; i++) {
                int e = (i * 256 + t) * 4;
                int m = e >> 5, k = e & 31;
                ra[i] = *(const float4*)(A + (size_t)(bm + m) * K + (kc + 1) * 32 + k);
                int bk = e >> 7, n = e & 127;
                rb[i] = *(const float4*)(B + (size_t)((kc + 1) * 32 + bk) * N + bn + n);
            }
        }
        #pragma unroll
        for (int ks = 0; ks < 4; ks++) {
            uint32_t af[4][4], bf[4][2];
            const int k = ks * 8 + tig;
            #pragma unroll
            for (int mi = 0; mi < 4; mi++) {
                int m = warpM * 64 + mi * 16 + gid;
                af[mi][0] = __float_as_uint(As[m * PADA + k]);
                af[mi][1] = __float_as_uint(As[(m + 8) * PADA + k]);
                af[mi][2] = __float_as_uint(As[m * PADA + k + 4]);
                af[mi][3] = __float_as_uint(As[(m + 8) * PADA + k + 4]);
            }
            #pragma unroll
            for (int ni = 0; ni < 4; ni++) {
                int n = warpN * 32 + ni * 8 + gid;
                bf[ni][0] = __float_as_uint(Bs[k * PADB + n]);
                bf[ni][1] = __float_as_uint(Bs[(k + 4) * PADB + n]);
            }
            #pragma unroll
            for (int mi = 0; mi < 4; mi++)
                #pragma unroll
                for (int ni = 0; ni < 4; ni++)
                    mma8(acc[mi][ni], af[mi], bf[ni]);
        }
        if (kc + 1 < NC) {
            __syncthreads();
            #pragma unroll
            for (int i = 0; i < 4; i++) {
                int e = (i * 256 + t) * 4;
                int m = e >> 5, k = e & 31;
                *(uint4*)&As[m * PADA + k] = cvt4(ra[i]);
                int bk = e >> 7, n = e & 127;
                *(uint4*)&Bs[bk * PADB + n] = cvt4(rb[i]);
            }
            __syncthreads();
        }
    }

    #pragma unroll
    for (int mi = 0; mi < 4; mi++) {
        #pragma unroll
        for (int ni = 0; ni < 4; ni++) {
            int r0 = bm + warpM * 64 + mi * 16 + gid;
            int c0 = bn + warpN * 32 + ni * 8 + tig * 2;
            float v0 = acc[mi][ni][0], v1 = acc[mi][ni][1];
            float v2 = acc[mi][ni][2], v3 = acc[mi][ni][3];
            if (bias) {
                float b0 = bias[c0], b1 = bias[c0 + 1];
                v0 += b0; v1 += b1; v2 += b0; v3 += b1;
            }
            if (act) {
                v0 = gelu_f(v0); v1 = gelu_f(v1);
                v2 = gelu_f(v2); v3 = gelu_f(v3);
            }
            if (resid) {
                // N == DIM here; gate per (batch,col)
                const float* gp0 = g_mod + (r0 >> 10) * 6 * DIM + gate_chunk * DIM + c0;
                const float* gp1 = g_mod + ((r0 + 8) >> 10) * 6 * DIM + gate_chunk * DIM + c0;
                float2 rr0 = *(const float2*)(resid + (size_t)r0 * N + c0);
                float2 rr1 = *(const float2*)(resid + (size_t)(r0 + 8) * N + c0);
                v0 = rr0.x + gp0[0] * v0;
                v1 = rr0.y + gp0[1] * v1;
                v2 = rr1.x + gp1[0] * v2;
                v3 = rr1.y + gp1[1] * v3;
            }
            *(float2*)(C + (size_t)r0 * N + c0)       = make_float2(v0, v1);
            *(float2*)(C + (size_t)(r0 + 8) * N + c0) = make_float2(v2, v3);
        }
    }
}

// ============ fused flash attention ============
// grid (SEQ/64, B*NH), 128 threads (4 warps). Each warp owns 16 q-rows.
#define FPAD 68
__global__ void __launch_bounds__(128)
flash_kernel()
{
    extern __shared__ float fs[];
    float* Qs = fs;                    // 64 x FPAD (pre-scaled by 0.125)
    float* Ks = Qs + 64 * FPAD;
    float* Vs = Ks + 64 * FPAD;
    float* Ps = Vs + 64 * FPAD;        // 64 x FPAD (per-warp 16-row slices)

    const int t = threadIdx.x, lane = t & 31, wid = t >> 5;
    const int gid = lane >> 2, tig = lane & 3;
    const int bh = blockIdx.y, b = bh >> 4, h = bh & 15;
    const int q0 = blockIdx.x * 64;
    const int row = wid * 16 + gid;    // this thread's first q-row (and row+8)

    // load Q tile (scaled)
    #pragma unroll
    for (int i = 0; i < 8; i++) {
        int e = (i * 128 + t) * 4;
        int r = e >> 6, c = e & 63;
        float4 v = *(const float4*)(g_qkv + ((size_t)(b * SEQ + q0 + r) * 3) * 1024 + h * 64 + c);
        v.x *= 0.125f; v.y *= 0.125f; v.z *= 0.125f; v.w *= 0.125f;
        *(uint4*)&Qs[r * FPAD + c] = cvt4(v);
    }

    float m_i[2] = { -1e30f, -1e30f };
    float l_i[2] = { 0.f, 0.f };
    float oacc[8][4];
    #pragma unroll
    for (int ni = 0; ni < 8; ni++)
        #pragma unroll
        for (int q = 0; q < 4; q++) oacc[ni][q] = 0.f;

    for (int kt = 0; kt < SEQ; kt += 64) {
        // load K, V tiles
        #pragma unroll
        for (int i = 0; i < 8; i++) {
            int e = (i * 128 + t) * 4;
            int r = e >> 6, c = e & 63;
            float4 kv = *(const float4*)(g_qkv + ((size_t)(b * SEQ + kt + r) * 3 + 1) * 1024 + h * 64 + c);
            *(uint4*)&Ks[r * FPAD + c] = cvt4(kv);
            float4 vv = *(const float4*)(g_qkv + ((size_t)(b * SEQ + kt + r) * 3 + 2) * 1024 + h * 64 + c);
            *(uint4*)&Vs[r * FPAD + c] = cvt4(vv);
        }
        __syncthreads();

        // S = Q @ K^T  (warp: 16 rows x 64 cols)
        float sacc[8][4];
        #pragma unroll
        for (int ni = 0; ni < 8; ni++)
            #pragma unroll
            for (int q = 0; q < 4; q++) sacc[ni][q] = 0.f;

        #pragma unroll
        for (int ks = 0; ks < 8; ks++) {
            const int k = ks * 8 + tig;
            uint32_t af[4];
            af[0] = __float_as_uint(Qs[row * FPAD + k]);
            af[1] = __float_as_uint(Qs[(row + 8) * FPAD + k]);
            af[2] = __float_as_uint(Qs[row * FPAD + k + 4]);
            af[3] = __float_as_uint(Qs[(row + 8) * FPAD + k + 4]);
            #pragma unroll
            for (int ni = 0; ni < 8; ni++) {
                int n = ni * 8 + gid;
                uint32_t bf[2];
                bf[0] = __float_as_uint(Ks[n * FPAD + k]);
                bf[1] = __float_as_uint(Ks[n * FPAD + k + 4]);
                mma8(sacc[ni], af, bf);
            }
        }

        // online softmax: row stats over the 64 new cols
        float rmax[2] = { -1e30f, -1e30f };
        #pragma unroll
        for (int ni = 0; ni < 8; ni++) {
            rmax[0] = fmaxf(rmax[0], fmaxf(sacc[ni][0], sacc[ni][1]));
            rmax[1] = fmaxf(rmax[1], fmaxf(sacc[ni][2], sacc[ni][3]));
        }
        #pragma unroll
        for (int w = 1; w <= 2; w <<= 1) {
            rmax[0] = fmaxf(rmax[0], __shfl_xor_sync(0xffffffff, rmax[0], w));
            rmax[1] = fmaxf(rmax[1], __shfl_xor_sync(0xffffffff, rmax[1], w));
        }
        float mnew0 = fmaxf(m_i[0], rmax[0]);
        float mnew1 = fmaxf(m_i[1], rmax[1]);
        float alpha0 = __expf(m_i[0] - mnew0);
        float alpha1 = __expf(m_i[1] - mnew1);
        m_i[0] = mnew0; m_i[1] = mnew1;

        float rsum[2] = { 0.f, 0.f };
        #pragma unroll
        for (int ni = 0; ni < 8; ni++) {
            float p0 = __expf(sacc[ni][0] - mnew0);
            float p1 = __expf(sacc[ni][1] - mnew0);
            float p2 = __expf(sacc[ni][2] - mnew1);
            float p3 = __expf(sacc[ni][3] - mnew1);
            rsum[0] += p0 + p1;
            rsum[1] += p2 + p3;
            int c = ni * 8 + tig * 2;
            Ps[row * FPAD + c]     = __uint_as_float(f2tf32(p0));
            Ps[row * FPAD + c + 1] = __uint_as_float(f2tf32(p1));
            Ps[(row + 8) * FPAD + c]     = __uint_as_float(f2tf32(p2));
            Ps[(row + 8) * FPAD + c + 1] = __uint_as_float(f2tf32(p3));
        }
        #pragma unroll
        for (int w = 1; w <= 2; w <<= 1) {
            rsum[0] += __shfl_xor_sync(0xffffffff, rsum[0], w);
            rsum[1] += __shfl_xor_sync(0xffffffff, rsum[1], w);
        }
        l_i[0] = l_i[0] * alpha0 + rsum[0];
        l_i[1] = l_i[1] * alpha1 + rsum[1];

        // rescale O accumulator
        #pragma unroll
        for (int ni = 0; ni < 8; ni++) {
            oacc[ni][0] *= alpha0; oacc[ni][1] *= alpha0;
            oacc[ni][2] *= alpha1; oacc[ni][3] *= alpha1;
        }
        __syncwarp();

        // O += P @ V
        #pragma unroll
        for (int ks = 0; ks < 8; ks++) {
            const int k = ks * 8 + tig;
            uint32_t af[4];
            af[0] = __float_as_uint(Ps[row * FPAD + k]);
            af[1] = __float_as_uint(Ps[(row + 8) * FPAD + k]);
            af[2] = __float_as_uint(Ps[row * FPAD + k + 4]);
            af[3] = __float_as_uint(Ps[(row + 8) * FPAD + k + 4]);
            #pragma unroll
            for (int ni = 0; ni < 8; ni++) {
                int n = ni * 8 + gid;
                uint32_t bf[2];
                bf[0] = __float_as_uint(Vs[k * FPAD + n]);
                bf[1] = __float_as_uint(Vs[(k + 4) * FPAD + n]);
                mma8(oacc[ni], af, bf);
            }
        }
        __syncthreads();   // before next K/V overwrite
    }

    float inv0 = __fdividef(1.0f, l_i[0]);
    float inv1 = __fdividef(1.0f, l_i[1]);
    #pragma unroll
    for (int ni = 0; ni < 8; ni++) {
        int c = h * 64 + ni * 8 + tig * 2;
        float* op0 = g_o + (size_t)(b * SEQ + q0 + row) * 1024 + c;
        float* op1 = g_o + (size_t)(b * SEQ + q0 + row + 8) * 1024 + c;
        *(float2*)op0 = make_float2(oacc[ni][0] * inv0, oacc[ni][1] * inv0);
        *(float2*)op1 = make_float2(oacc[ni][2] * inv1, oacc[ni][3] * inv1);
    }
}

// ---------------- adaLN modulation ----------------
__global__ void ada_kernel(const float* __restrict__ c,
                           const float* __restrict__ w_ada,
                           const float* __restrict__ b_ada)
{
    int idx = blockIdx.x * blockDim.x + threadIdx.x;
    if (idx >= BATCH * 6 * DIM) return;
    int j = idx % (6 * DIM);
    int b = idx / (6 * DIM);
    float s = b_ada[j];
    const float* crow = c + b * DIM;
    #pragma unroll 4
    for (int k = 0; k < DIM; k++)
        s += crow[k] * w_ada[k * (6 * DIM) + j];
    g_mod[idx] = s;
}

// ---------------- LayerNorm + modulate ----------------
__global__ void ln_mod_kernel(const float* __restrict__ x,
                              const float* __restrict__ w,
                              int shift_chunk, int scale_chunk,
                              float* __restrict__ out)
{
    int row = blockIdx.x;
    int b = row >> 10;
    int t = threadIdx.x;
    const float* xr = x + (size_t)row * DIM;
    float4 v = *(const float4*)(xr + t * 4);
    float sum = v.x + v.y + v.z + v.w;
    float sq  = v.x*v.x + v.y*v.y + v.z*v.z + v.w*v.w;

    __shared__ float s1[256], s2[256];
    s1[t] = sum; s2[t] = sq;
    __syncthreads();
    for (int off = 128; off > 0; off >>= 1) {
        if (t < off) { s1[t] += s1[t + off]; s2[t] += s2[t + off]; }
        __syncthreads();
    }
    float mean = s1[0] * (1.0f / DIM);
    float var  = s2[0] * (1.0f / DIM) - mean * mean;
    float rstd = rsqrtf(var + LN_EPS);

    const float* shiftp = g_mod + b * 6 * DIM + shift_chunk * DIM;
    const float* scalep = g_mod + b * 6 * DIM + scale_chunk * DIM;
    float* orow = out + (size_t)row * DIM;
    #pragma unroll
    for (int u = 0; u < 4; u++) {
        int col = t * 4 + u;
        float xv = (u == 0) ? v.x : (u == 1) ? v.y : (u == 2) ? v.z : v.w;
        float y = (xv - mean) * rstd * w[col];
        orow[col] = y * (1.0f + scalep[col]) + shiftp[col];
    }
}

// ---------------- RoPE ----------------
__global__ void rope_kernel(const float* __restrict__ cosb,
                            const float* __restrict__ sinb)
{
    int idx = blockIdx.x * blockDim.x + threadIdx.x;
    if (idx >= BATCH * SEQ * NH * 32) return;
    int i = idx & 31;
    int h = (idx >> 5) & 15;
    int s = (idx >> 9) & 1023;
    int b = idx >> 19;
    float co = cosb[s * 32 + i];
    float si = sinb[s * 32 + i];
    #pragma unroll
    for (int p = 0; p < 2; p++) {
        int base = ((((b * SEQ + s) * 3 + p) * NH) + h) * HD;
        float t1 = g_qkv[base + i];
        float t2 = g_qkv[base + 32 + i];
        g_qkv[base + i]      = t1 * co - t2 * si;
        g_qkv[base + 32 + i] = t2 * co + t1 * si;
    }
}

// ---------------- launch ----------------
extern "C" void kernel_launch(void* const* d_in, const int* in_sizes, int n_in,
                              void* d_out, int out_size)
{
    const float* x          = (const float*)d_in[0];
    const float* cosb       = (const float*)d_in[1];
    const float* sinb       = (const float*)d_in[2];
    const float* c          = (const float*)d_in[3];
    const float* w_ln1      = (const float*)d_in[4];
    const float* w_ln2      = (const float*)d_in[5];
    const float* w_qkv      = (const float*)d_in[6];
    const float* w_attn_out = (const float*)d_in[7];
    const float* w_mlp1     = (const float*)d_in[8];
    const float* b_mlp1     = (const float*)d_in[9];
    const float* w_mlp2     = (const float*)d_in[10];
    const float* b_mlp2     = (const float*)d_in[11];
    const float* w_ada      = (const float*)d_in[12];
    const float* b_ada      = (const float*)d_in[13];
    float* out = (float*)d_out;

    float *p_h, *p_qkv, *p_o, *p_tmp, *p_x2, *p_mid;
    cudaGetSymbolAddress((void**)&p_h,   g_h);
    cudaGetSymbolAddress((void**)&p_qkv, g_qkv);
    cudaGetSymbolAddress((void**)&p_o,   g_o);
    cudaGetSymbolAddress((void**)&p_tmp, g_tmp);
    cudaGetSymbolAddress((void**)&p_x2,  g_x2);
    cudaGetSymbolAddress((void**)&p_mid, g_mid);

    const int FSM = 4 * 64 * FPAD * sizeof(float);
    cudaFuncSetAttribute(flash_kernel,
                         cudaFuncAttributeMaxDynamicSharedMemorySize, FSM);

    // 1. adaLN modulation
    ada_kernel<<<(BATCH * 6 * DIM + 255) / 256, 256>>>(c, w_ada, b_ada);

    // 2. LN1 + modulate
    ln_mod_kernel<<<BS, 256>>>(x, w_ln1, 0, 1, p_h);

    // 3. qkv = h @ w_qkv
    tgemm_kernel<<<dim3(3 * DIM / 128, BS / 128), 256>>>(
        p_h, w_qkv, nullptr, nullptr, p_qkv, BS, 3 * DIM, DIM, 0, 0);

    // 4. RoPE
    rope_kernel<<<(BATCH * SEQ * NH * 32 + 255) / 256, 256>>>(cosb, sinb);

    // 5. fused attention (QK^T -> softmax -> PV)
    flash_kernel<<<dim3(SEQ / 64, BATCH * NH), 128, FSM>>>();

    // 6. x2 = x + gate_msa * (o @ w_attn_out)   [fused residual]
    tgemm_kernel<<<dim3(DIM / 128, BS / 128), 256>>>(
        p_o, w_attn_out, nullptr, x, p_x2, BS, DIM, DIM, 0, 2);

    // 7. LN2 + modulate
    ln_mod_kernel<<<BS, 256>>>(p_x2, w_ln2, 3, 4, p_h);

    // 8. mid = gelu(h @ w_mlp1 + b_mlp1)
    tgemm_kernel<<<dim3(MLP_HID / 128, BS / 128), 256>>>(
        p_h, w_mlp1, b_mlp1, nullptr, p_mid, BS, MLP_HID, DIM, 1, 0);

    // 9. out = x2 + gate_mlp * (mid @ w_mlp2 + b_mlp2)   [fused residual]
    tgemm_kernel<<<dim3(DIM / 128, BS / 128), 256>>>(
        p_mid, w_mlp2, b_mlp2, p_x2, out, BS, DIM, MLP_HID, 0, 5);
}

// round 5
// speedup vs baseline: 3.3434x; 1.2312x over previous
#include <cuda_runtime.h>
#include <cuda_bf16.h>
#include <math.h>
#include <stdint.h>

#define DIM 1024
#define NH 16
#define HD 64
#define BATCH 4
#define SEQ 1024
#define BS (BATCH*SEQ)
#define MLP_HID 4096
#define LN_EPS 1e-5f

// ---------------- scratch ----------------
__device__ float g_mod[BATCH * 6 * DIM];
__device__ float g_h[BS * DIM];
__device__ float g_qkv[BS * 3 * DIM];
__device__ float g_o[BS * DIM];
__device__ float g_x2[BS * DIM];
__device__ float g_mid[BS * MLP_HID];

// ================= helpers =================
__device__ __forceinline__ uint32_t f2tf32(float f) {
    uint32_t r;
    asm("cvt.rna.tf32.f32 %0, %1;" : "=r"(r) : "f"(f));
    return r;
}
__device__ __forceinline__ uint4 cvt4(float4 v) {
    uint4 u;
    u.x = f2tf32(v.x); u.y = f2tf32(v.y);
    u.z = f2tf32(v.z); u.w = f2tf32(v.w);
    return u;
}
__device__ __forceinline__ void mma8(float* c, const uint32_t* a, const uint32_t* b) {
    asm volatile(
        "mma.sync.aligned.m16n8k8.row.col.f32.tf32.tf32.f32 "
        "{%0,%1,%2,%3}, {%4,%5,%6,%7}, {%8,%9}, {%0,%1,%2,%3};"
        : "+f"(c[0]), "+f"(c[1]), "+f"(c[2]), "+f"(c[3])
        : "r"(a[0]), "r"(a[1]), "r"(a[2]), "r"(a[3]), "r"(b[0]), "r"(b[1]));
}
__device__ __forceinline__ float gelu_f(float u) {
    float y = 0.7978845608028654f * (u + 0.044715f * u * u * u);
    float e = __expf(2.0f * y);
    return u * (1.0f - __fdividef(1.0f, e + 1.0f));
}

#define CP16(smem, gmem) \
    asm volatile("cp.async.cg.shared.global [%0], [%1], 16;" :: "r"(smem), "l"(gmem))
#define CP_COMMIT() asm volatile("cp.async.commit_group;" ::: "memory")
#define CP_WAIT1()  asm volatile("cp.async.wait_group 1;" ::: "memory")

// ============ tf32 mma GEMM, 3-stage cp.async pipeline ============
// 128x128 CTA tile, BK=32, 256 threads = 8 warps (2M x 4N), warp tile 64x32.
#define PADA 36
#define PADB 136
#define ASZ (128 * PADA)
#define BSZ (32 * PADB)
#define STG (ASZ + BSZ)
#define NSTAGE 3
#define GSMEM (NSTAGE * STG * 4)

__global__ void __launch_bounds__(256)
tgemm_kernel(const float* __restrict__ A,
             const float* __restrict__ B,
             const float* __restrict__ bias,
             const float* __restrict__ resid,
             float* __restrict__ C,
             int M, int N, int K, int act, int gate_chunk)
{
    extern __shared__ float fs[];
    const uint32_t smb = (uint32_t)__cvta_generic_to_shared(fs);

    const int t = threadIdx.x, lane = t & 31, wid = t >> 5;
    const int warpM = wid >> 2, warpN = wid & 3;
    const int bm = blockIdx.y * 128, bn = blockIdx.x * 128;
    const int gid = lane >> 2, tig = lane & 3;

    // per-thread load slots (4 x 16B for A, 4 x 16B for B)
    const int am = (t * 4) >> 5;            // base A row for i=0 (rows advance by 32 per i)
    const int ak = (t * 4) & 31;
    const int bk = (t * 4) >> 7;            // base B k-row (advance 8 per i)
    const int bnn = (t * 4) & 127;

    float acc[4][4][4];
    #pragma unroll
    for (int i = 0; i < 4; i++)
        #pragma unroll
        for (int j = 0; j < 4; j++)
            #pragma unroll
            for (int q = 0; q < 4; q++) acc[i][j][q] = 0.f;

    const int NC = K >> 5;

    // ---- issue loads for one stage ----
    auto issue = [&](int stage, int kc) {
        uint32_t abase = smb + (uint32_t)(stage * STG) * 4u;
        uint32_t bbase = abase + (uint32_t)ASZ * 4u;
        #pragma unroll
        for (int i = 0; i < 4; i++) {
            int m = am + i * 32;
            CP16(abase + (uint32_t)(m * PADA + ak) * 4u,
                 A + (size_t)(bm + m) * K + kc * 32 + ak);
        }
        #pragma unroll
        for (int i = 0; i < 4; i++) {
            int kk = bk + i * 8;
            CP16(bbase + (uint32_t)(kk * PADB + bnn) * 4u,
                 B + (size_t)(kc * 32 + kk) * N + bn + bnn);
        }
    };

    // prologue: stages 0,1
    issue(0, 0); CP_COMMIT();
    if (NC > 1) issue(1, 1);
    CP_COMMIT();

    for (int kc = 0; kc < NC; kc++) {
        CP_WAIT1();
        __syncthreads();

        // issue stage kc+2 (now safe: everyone done computing stage kc-1)
        if (kc + 2 < NC) issue((kc + 2) % NSTAGE, kc + 2);
        CP_COMMIT();

        const float* As = fs + (kc % NSTAGE) * STG;
        const float* Bs = As + ASZ;

        #pragma unroll
        for (int ks = 0; ks < 4; ks++) {
            uint32_t af[4][4], bf[4][2];
            const int k = ks * 8 + tig;
            #pragma unroll
            for (int mi = 0; mi < 4; mi++) {
                int m = warpM * 64 + mi * 16 + gid;
                af[mi][0] = f2tf32(As[m * PADA + k]);
                af[mi][1] = f2tf32(As[(m + 8) * PADA + k]);
                af[mi][2] = f2tf32(As[m * PADA + k + 4]);
                af[mi][3] = f2tf32(As[(m + 8) * PADA + k + 4]);
            }
            #pragma unroll
            for (int ni = 0; ni < 4; ni++) {
                int n = warpN * 32 + ni * 8 + gid;
                bf[ni][0] = f2tf32(Bs[k * PADB + n]);
                bf[ni][1] = f2tf32(Bs[(k + 4) * PADB + n]);
            }
            #pragma unroll
            for (int mi = 0; mi < 4; mi++)
                #pragma unroll
                for (int ni = 0; ni < 4; ni++)
                    mma8(acc[mi][ni], af[mi], bf[ni]);
        }
    }

    // ---- epilogue ----
    #pragma unroll
    for (int mi = 0; mi < 4; mi++) {
        #pragma unroll
        for (int ni = 0; ni < 4; ni++) {
            int r0 = bm + warpM * 64 + mi * 16 + gid;
            int c0 = bn + warpN * 32 + ni * 8 + tig * 2;
            float v0 = acc[mi][ni][0], v1 = acc[mi][ni][1];
            float v2 = acc[mi][ni][2], v3 = acc[mi][ni][3];
            if (bias) {
                float b0 = bias[c0], b1 = bias[c0 + 1];
                v0 += b0; v1 += b1; v2 += b0; v3 += b1;
            }
            if (act) {
                v0 = gelu_f(v0); v1 = gelu_f(v1);
                v2 = gelu_f(v2); v3 = gelu_f(v3);
            }
            if (resid) {
                const float* gp0 = g_mod + (r0 >> 10) * 6 * DIM + gate_chunk * DIM + c0;
                const float* gp1 = g_mod + ((r0 + 8) >> 10) * 6 * DIM + gate_chunk * DIM + c0;
                float2 rr0 = *(const float2*)(resid + (size_t)r0 * N + c0);
                float2 rr1 = *(const float2*)(resid + (size_t)(r0 + 8) * N + c0);
                v0 = rr0.x + gp0[0] * v0;
                v1 = rr0.y + gp0[1] * v1;
                v2 = rr1.x + gp1[0] * v2;
                v3 = rr1.y + gp1[1] * v3;
            }
            *(float2*)(C + (size_t)r0 * N + c0)       = make_float2(v0, v1);
            *(float2*)(C + (size_t)(r0 + 8) * N + c0) = make_float2(v2, v3);
        }
    }
}

// ============ fused flash attention ============
#define FPAD 68
__global__ void __launch_bounds__(128)
flash_kernel()
{
    extern __shared__ float fsm[];
    float* Qs = fsm;
    float* Ks = Qs + 64 * FPAD;
    float* Vs = Ks + 64 * FPAD;
    float* Ps = Vs + 64 * FPAD;

    const int t = threadIdx.x, lane = t & 31, wid = t >> 5;
    const int gid = lane >> 2, tig = lane & 3;
    const int bh = blockIdx.y, b = bh >> 4, h = bh & 15;
    const int q0 = blockIdx.x * 64;
    const int row = wid * 16 + gid;

    #pragma unroll
    for (int i = 0; i < 8; i++) {
        int e = (i * 128 + t) * 4;
        int r = e >> 6, c = e & 63;
        float4 v = *(const float4*)(g_qkv + ((size_t)(b * SEQ + q0 + r) * 3) * 1024 + h * 64 + c);
        v.x *= 0.125f; v.y *= 0.125f; v.z *= 0.125f; v.w *= 0.125f;
        *(uint4*)&Qs[r * FPAD + c] = cvt4(v);
    }

    float m_i[2] = { -1e30f, -1e30f };
    float l_i[2] = { 0.f, 0.f };
    float oacc[8][4];
    #pragma unroll
    for (int ni = 0; ni < 8; ni++)
        #pragma unroll
        for (int q = 0; q < 4; q++) oacc[ni][q] = 0.f;

    for (int kt = 0; kt < SEQ; kt += 64) {
        #pragma unroll
        for (int i = 0; i < 8; i++) {
            int e = (i * 128 + t) * 4;
            int r = e >> 6, c = e & 63;
            float4 kv = *(const float4*)(g_qkv + ((size_t)(b * SEQ + kt + r) * 3 + 1) * 1024 + h * 64 + c);
            *(uint4*)&Ks[r * FPAD + c] = cvt4(kv);
            float4 vv = *(const float4*)(g_qkv + ((size_t)(b * SEQ + kt + r) * 3 + 2) * 1024 + h * 64 + c);
            *(uint4*)&Vs[r * FPAD + c] = cvt4(vv);
        }
        __syncthreads();

        float sacc[8][4];
        #pragma unroll
        for (int ni = 0; ni < 8; ni++)
            #pragma unroll
            for (int q = 0; q < 4; q++) sacc[ni][q] = 0.f;

        #pragma unroll
        for (int ks = 0; ks < 8; ks++) {
            const int k = ks * 8 + tig;
            uint32_t af[4];
            af[0] = __float_as_uint(Qs[row * FPAD + k]);
            af[1] = __float_as_uint(Qs[(row + 8) * FPAD + k]);
            af[2] = __float_as_uint(Qs[row * FPAD + k + 4]);
            af[3] = __float_as_uint(Qs[(row + 8) * FPAD + k + 4]);
            #pragma unroll
            for (int ni = 0; ni < 8; ni++) {
                int n = ni * 8 + gid;
                uint32_t bf[2];
                bf[0] = __float_as_uint(Ks[n * FPAD + k]);
                bf[1] = __float_as_uint(Ks[n * FPAD + k + 4]);
                mma8(sacc[ni], af, bf);
            }
        }

        float rmax[2] = { -1e30f, -1e30f };
        #pragma unroll
        for (int ni = 0; ni < 8; ni++) {
            rmax[0] = fmaxf(rmax[0], fmaxf(sacc[ni][0], sacc[ni][1]));
            rmax[1] = fmaxf(rmax[1], fmaxf(sacc[ni][2], sacc[ni][3]));
        }
        #pragma unroll
        for (int w = 1; w <= 2; w <<= 1) {
            rmax[0] = fmaxf(rmax[0], __shfl_xor_sync(0xffffffff, rmax[0], w));
            rmax[1] = fmaxf(rmax[1], __shfl_xor_sync(0xffffffff, rmax[1], w));
        }
        float mnew0 = fmaxf(m_i[0], rmax[0]);
        float mnew1 = fmaxf(m_i[1], rmax[1]);
        float alpha0 = __expf(m_i[0] - mnew0);
        float alpha1 = __expf(m_i[1] - mnew1);
        m_i[0] = mnew0; m_i[1] = mnew1;

        float rsum[2] = { 0.f, 0.f };
        #pragma unroll
        for (int ni = 0; ni < 8; ni++) {
            float p0 = __expf(sacc[ni][0] - mnew0);
            float p1 = __expf(sacc[ni][1] - mnew0);
            float p2 = __expf(sacc[ni][2] - mnew1);
            float p3 = __expf(sacc[ni][3] - mnew1);
            rsum[0] += p0 + p1;
            rsum[1] += p2 + p3;
            int c = ni * 8 + tig * 2;
            Ps[row * FPAD + c]     = __uint_as_float(f2tf32(p0));
            Ps[row * FPAD + c + 1] = __uint_as_float(f2tf32(p1));
            Ps[(row + 8) * FPAD + c]     = __uint_as_float(f2tf32(p2));
            Ps[(row + 8) * FPAD + c + 1] = __uint_as_float(f2tf32(p3));
        }
        #pragma unroll
        for (int w = 1; w <= 2; w <<= 1) {
            rsum[0] += __shfl_xor_sync(0xffffffff, rsum[0], w);
            rsum[1] += __shfl_xor_sync(0xffffffff, rsum[1], w);
        }
        l_i[0] = l_i[0] * alpha0 + rsum[0];
        l_i[1] = l_i[1] * alpha1 + rsum[1];

        #pragma unroll
        for (int ni = 0; ni < 8; ni++) {
            oacc[ni][0] *= alpha0; oacc[ni][1] *= alpha0;
            oacc[ni][2] *= alpha1; oacc[ni][3] *= alpha1;
        }
        __syncwarp();

        #pragma unroll
        for (int ks = 0; ks < 8; ks++) {
            const int k = ks * 8 + tig;
            uint32_t af[4];
            af[0] = __float_as_uint(Ps[row * FPAD + k]);
            af[1] = __float_as_uint(Ps[(row + 8) * FPAD + k]);
            af[2] = __float_as_uint(Ps[row * FPAD + k + 4]);
            af[3] = __float_as_uint(Ps[(row + 8) * FPAD + k + 4]);
            #pragma unroll
            for (int ni = 0; ni < 8; ni++) {
                int n = ni * 8 + gid;
                uint32_t bf[2];
                bf[0] = __float_as_uint(Vs[k * FPAD + n]);
                bf[1] = __float_as_uint(Vs[(k + 4) * FPAD + n]);
                mma8(oacc[ni], af, bf);
            }
        }
        __syncthreads();
    }

    float inv0 = __fdividef(1.0f, l_i[0]);
    float inv1 = __fdividef(1.0f, l_i[1]);
    #pragma unroll
    for (int ni = 0; ni < 8; ni++) {
        int c = h * 64 + ni * 8 + tig * 2;
        float* op0 = g_o + (size_t)(b * SEQ + q0 + row) * 1024 + c;
        float* op1 = g_o + (size_t)(b * SEQ + q0 + row + 8) * 1024 + c;
        *(float2*)op0 = make_float2(oacc[ni][0] * inv0, oacc[ni][1] * inv0);
        *(float2*)op1 = make_float2(oacc[ni][2] * inv1, oacc[ni][3] * inv1);
    }
}

// ---------------- adaLN modulation ----------------
__global__ void ada_kernel(const float* __restrict__ c,
                           const float* __restrict__ w_ada,
                           const float* __restrict__ b_ada)
{
    int idx = blockIdx.x * blockDim.x + threadIdx.x;
    if (idx >= BATCH * 6 * DIM) return;
    int j = idx % (6 * DIM);
    int b = idx / (6 * DIM);
    float s = b_ada[j];
    const float* crow = c + b * DIM;
    #pragma unroll 4
    for (int k = 0; k < DIM; k++)
        s += crow[k] * w_ada[k * (6 * DIM) + j];
    g_mod[idx] = s;
}

// ---------------- LayerNorm + modulate ----------------
__global__ void ln_mod_kernel(const float* __restrict__ x,
                              const float* __restrict__ w,
                              int shift_chunk, int scale_chunk,
                              float* __restrict__ out)
{
    int row = blockIdx.x;
    int b = row >> 10;
    int t = threadIdx.x;
    const float* xr = x + (size_t)row * DIM;
    float4 v = *(const float4*)(xr + t * 4);
    float sum = v.x + v.y + v.z + v.w;
    float sq  = v.x*v.x + v.y*v.y + v.z*v.z + v.w*v.w;

    __shared__ float s1[256], s2[256];
    s1[t] = sum; s2[t] = sq;
    __syncthreads();
    for (int off = 128; off > 0; off >>= 1) {
        if (t < off) { s1[t] += s1[t + off]; s2[t] += s2[t + off]; }
        __syncthreads();
    }
    float mean = s1[0] * (1.0f / DIM);
    float var  = s2[0] * (1.0f / DIM) - mean * mean;
    float rstd = rsqrtf(var + LN_EPS);

    const float* shiftp = g_mod + b * 6 * DIM + shift_chunk * DIM;
    const float* scalep = g_mod + b * 6 * DIM + scale_chunk * DIM;
    float* orow = out + (size_t)row * DIM;
    #pragma unroll
    for (int u = 0; u < 4; u++) {
        int col = t * 4 + u;
        float xv = (u == 0) ? v.x : (u == 1) ? v.y : (u == 2) ? v.z : v.w;
        float y = (xv - mean) * rstd * w[col];
        orow[col] = y * (1.0f + scalep[col]) + shiftp[col];
    }
}

// ---------------- RoPE ----------------
__global__ void rope_kernel(const float* __restrict__ cosb,
                            const float* __restrict__ sinb)
{
    int idx = blockIdx.x * blockDim.x + threadIdx.x;
    if (idx >= BATCH * SEQ * NH * 32) return;
    int i = idx & 31;
    int h = (idx >> 5) & 15;
    int s = (idx >> 9) & 1023;
    int b = idx >> 19;
    float co = cosb[s * 32 + i];
    float si = sinb[s * 32 + i];
    #pragma unroll
    for (int p = 0; p < 2; p++) {
        int base = ((((b * SEQ + s) * 3 + p) * NH) + h) * HD;
        float t1 = g_qkv[base + i];
        float t2 = g_qkv[base + 32 + i];
        g_qkv[base + i]      = t1 * co - t2 * si;
        g_qkv[base + 32 + i] = t2 * co + t1 * si;
    }
}

// ---------------- launch ----------------
extern "C" void kernel_launch(void* const* d_in, const int* in_sizes, int n_in,
                              void* d_out, int out_size)
{
    const float* x          = (const float*)d_in[0];
    const float* cosb       = (const float*)d_in[1];
    const float* sinb       = (const float*)d_in[2];
    const float* c          = (const float*)d_in[3];
    const float* w_ln1      = (const float*)d_in[4];
    const float* w_ln2      = (const float*)d_in[5];
    const float* w_qkv      = (const float*)d_in[6];
    const float* w_attn_out = (const float*)d_in[7];
    const float* w_mlp1     = (const float*)d_in[8];
    const float* b_mlp1     = (const float*)d_in[9];
    const float* w_mlp2     = (const float*)d_in[10];
    const float* b_mlp2     = (const float*)d_in[11];
    const float* w_ada      = (const float*)d_in[12];
    const float* b_ada      = (const float*)d_in[13];
    float* out = (float*)d_out;

    float *p_h, *p_qkv, *p_o, *p_x2, *p_mid;
    cudaGetSymbolAddress((void**)&p_h,   g_h);
    cudaGetSymbolAddress((void**)&p_qkv, g_qkv);
    cudaGetSymbolAddress((void**)&p_o,   g_o);
    cudaGetSymbolAddress((void**)&p_x2,  g_x2);
    cudaGetSymbolAddress((void**)&p_mid, g_mid);

    const int FSM = 4 * 64 * FPAD * sizeof(float);
    cudaFuncSetAttribute(flash_kernel,
                         cudaFuncAttributeMaxDynamicSharedMemorySize, FSM);
    cudaFuncSetAttribute(tgemm_kernel,
                         cudaFuncAttributeMaxDynamicSharedMemorySize, GSMEM);

    ada_kernel<<<(BATCH * 6 * DIM + 255) / 256, 256>>>(c, w_ada, b_ada);
    ln_mod_kernel<<<BS, 256>>>(x, w_ln1, 0, 1, p_h);

    tgemm_kernel<<<dim3(3 * DIM / 128, BS / 128), 256, GSMEM>>>(
        p_h, w_qkv, nullptr, nullptr, p_qkv, BS, 3 * DIM, DIM, 0, 0);

    rope_kernel<<<(BATCH * SEQ * NH * 32 + 255) / 256, 256>>>(cosb, sinb);

    flash_kernel<<<dim3(SEQ / 64, BATCH * NH), 128, FSM>>>();

    tgemm_kernel<<<dim3(DIM / 128, BS / 128), 256, GSMEM>>>(
        p_o, w_attn_out, nullptr, x, p_x2, BS, DIM, DIM, 0, 2);

    ln_mod_kernel<<<BS, 256>>>(p_x2, w_ln2, 3, 4, p_h);

    tgemm_kernel<<<dim3(MLP_HID / 128, BS / 128), 256, GSMEM>>>(
        p_h, w_mlp1, b_mlp1, nullptr, p_mid, BS, MLP_HID, DIM, 1, 0);

    tgemm_kernel<<<dim3(DIM / 128, BS / 128), 256, GSMEM>>>(
        p_mid, w_mlp2, b_mlp2, p_x2, out, BS, DIM, MLP_HID, 0, 5);
}

// round 6
// speedup vs baseline: 5.4743x; 1.6374x over previous
#include <cuda_runtime.h>
#include <cuda_fp16.h>
#include <math.h>
#include <stdint.h>

#define DIM 1024
#define NH 16
#define HD 64
#define BATCH 4
#define SEQ 1024
#define BS (BATCH*SEQ)
#define MLP_HID 4096
#define LN_EPS 1e-5f

// ---------------- scratch ----------------
__device__ float  g_mod[BATCH * 6 * DIM];
__device__ __half g_h[BS * DIM];
__device__ __half g_qkv[BS * 3 * DIM];
__device__ __half g_o[BS * DIM];
__device__ float  g_x2[BS * DIM];
__device__ __half g_mid[BS * MLP_HID];
// converted weights: qkv | attn | mlp1 | mlp2
#define WO_QKV  0
#define WO_ATTN (3*DIM*DIM)
#define WO_MLP1 (WO_ATTN + DIM*DIM)
#define WO_MLP2 (WO_MLP1 + DIM*MLP_HID)
#define W_TOTAL (WO_MLP2 + MLP_HID*DIM)
__device__ __half g_wh[W_TOTAL];

// ================= helpers =================
__device__ __forceinline__ void mma16(float* c, const uint32_t* a, const uint32_t* b) {
    asm volatile(
        "mma.sync.aligned.m16n8k16.row.col.f32.f16.f16.f32 "
        "{%0,%1,%2,%3}, {%4,%5,%6,%7}, {%8,%9}, {%0,%1,%2,%3};"
        : "+f"(c[0]), "+f"(c[1]), "+f"(c[2]), "+f"(c[3])
        : "r"(a[0]), "r"(a[1]), "r"(a[2]), "r"(a[3]), "r"(b[0]), "r"(b[1]));
}
__device__ __forceinline__ void ldsm4(uint32_t* r, uint32_t addr) {
    asm volatile("ldmatrix.sync.aligned.m8n8.x4.shared.b16 {%0,%1,%2,%3}, [%4];"
        : "=r"(r[0]), "=r"(r[1]), "=r"(r[2]), "=r"(r[3]) : "r"(addr));
}
__device__ __forceinline__ void ldsm2t(uint32_t* r, uint32_t addr) {
    asm volatile("ldmatrix.sync.aligned.m8n8.x2.trans.shared.b16 {%0,%1}, [%2];"
        : "=r"(r[0]), "=r"(r[1]) : "r"(addr));
}
__device__ __forceinline__ uint32_t packh2(float a, float b) {
    __half2 h = __floats2half2_rn(a, b);
    return *(uint32_t*)&h;
}
__device__ __forceinline__ float gelu_f(float u) {
    float y = 0.7978845608028654f * (u + 0.044715f * u * u * u);
    float e = __expf(2.0f * y);
    return u * (1.0f - __fdividef(1.0f, e + 1.0f));
}

#define CP16(smem, gmem) \
    asm volatile("cp.async.cg.shared.global [%0], [%1], 16;" :: "r"(smem), "l"(gmem))
#define CP_COMMIT() asm volatile("cp.async.commit_group;" ::: "memory")
#define CP_WAIT1()  asm volatile("cp.async.wait_group 1;" ::: "memory")

// ---------------- fp32 -> fp16 convert ----------------
__global__ void cvt_kernel(const float* __restrict__ src, __half* __restrict__ dst, int n)
{
    int i = (blockIdx.x * blockDim.x + threadIdx.x) * 8;
    if (i >= n) return;
    float4 v0 = *(const float4*)(src + i);
    float4 v1 = *(const float4*)(src + i + 4);
    uint4 u;
    u.x = packh2(v0.x, v0.y); u.y = packh2(v0.z, v0.w);
    u.z = packh2(v1.x, v1.y); u.w = packh2(v1.z, v1.w);
    *(uint4*)(dst + i) = u;
}

// ============ fp16 mma GEMM, 3-stage cp.async pipeline ============
// 128x128 CTA tile, BK=32, 256 threads = 8 warps (2M x 4N), warp tile 64x32.
#define PADA 40        // halves per A row
#define PADB 136       // halves per B row
#define ASZH (128 * PADA)
#define BSZH (32 * PADB)
#define STGB ((ASZH + BSZH) * 2)
#define NSTAGE 3
#define GSMEM (NSTAGE * STGB)

__global__ void __launch_bounds__(256)
tgemm_kernel(const __half* __restrict__ A,
             const __half* __restrict__ B,
             const float* __restrict__ bias,
             const float* __restrict__ resid,
             void* __restrict__ C,
             int M, int N, int K, int act, int gate_chunk, int out_half)
{
    extern __shared__ char fsraw[];
    const uint32_t smb = (uint32_t)__cvta_generic_to_shared(fsraw);

    const int t = threadIdx.x, lane = t & 31, wid = t >> 5;
    const int warpM = wid >> 2, warpN = wid & 3;
    const int bm = blockIdx.y * 128, bn = blockIdx.x * 128;
    const int gid = lane >> 2, tig = lane & 3;

    const int am = (t * 8) >> 5;     // A row for i=0 (advance 64 per i)
    const int ak = (t * 8) & 31;
    const int bk = (t * 8) >> 7;     // B k-row (advance 16 per i)
    const int bnn = (t * 8) & 127;

    float acc[4][4][4];
    #pragma unroll
    for (int i = 0; i < 4; i++)
        #pragma unroll
        for (int j = 0; j < 4; j++)
            #pragma unroll
            for (int q = 0; q < 4; q++) acc[i][j][q] = 0.f;

    const int NC = K >> 5;

    auto issue = [&](int stage, int kc) {
        uint32_t abase = smb + (uint32_t)(stage * STGB);
        uint32_t bbase = abase + (uint32_t)(ASZH * 2);
        #pragma unroll
        for (int i = 0; i < 2; i++) {
            int m = am + i * 64;
            CP16(abase + (uint32_t)(m * PADA + ak) * 2u,
                 A + (size_t)(bm + m) * K + kc * 32 + ak);
        }
        #pragma unroll
        for (int i = 0; i < 2; i++) {
            int kk = bk + i * 16;
            CP16(bbase + (uint32_t)(kk * PADB + bnn) * 2u,
                 B + (size_t)(kc * 32 + kk) * N + bn + bnn);
        }
    };

    issue(0, 0); CP_COMMIT();
    if (NC > 1) issue(1, 1);
    CP_COMMIT();

    const int arow = warpM * 64 + (lane & 15);
    const int akof = (lane >> 4) * 8;
    const int bkl = lane & 15;

    for (int kc = 0; kc < NC; kc++) {
        CP_WAIT1();
        __syncthreads();
        if (kc + 2 < NC) issue((kc + 2) % NSTAGE, kc + 2);
        CP_COMMIT();

        const uint32_t sA = smb + (uint32_t)((kc % NSTAGE) * STGB);
        const uint32_t sB = sA + (uint32_t)(ASZH * 2);

        #pragma unroll
        for (int ks = 0; ks < 2; ks++) {
            uint32_t af[4][4], bf[4][2];
            #pragma unroll
            for (int mi = 0; mi < 4; mi++) {
                int row = arow + mi * 16;
                ldsm4(af[mi], sA + (uint32_t)(row * PADA + ks * 16 + akof) * 2u);
            }
            #pragma unroll
            for (int ni = 0; ni < 4; ni++) {
                int n0 = warpN * 32 + ni * 8;
                int k = ks * 16 + bkl;
                ldsm2t(bf[ni], sB + (uint32_t)(k * PADB + n0) * 2u);
            }
            #pragma unroll
            for (int mi = 0; mi < 4; mi++)
                #pragma unroll
                for (int ni = 0; ni < 4; ni++)
                    mma16(acc[mi][ni], af[mi], bf[ni]);
        }
    }

    // ---- epilogue ----
    #pragma unroll
    for (int mi = 0; mi < 4; mi++) {
        #pragma unroll
        for (int ni = 0; ni < 4; ni++) {
            int r0 = bm + warpM * 64 + mi * 16 + gid;
            int c0 = bn + warpN * 32 + ni * 8 + tig * 2;
            float v0 = acc[mi][ni][0], v1 = acc[mi][ni][1];
            float v2 = acc[mi][ni][2], v3 = acc[mi][ni][3];
            if (bias) {
                float b0 = bias[c0], b1 = bias[c0 + 1];
                v0 += b0; v1 += b1; v2 += b0; v3 += b1;
            }
            if (act) {
                v0 = gelu_f(v0); v1 = gelu_f(v1);
                v2 = gelu_f(v2); v3 = gelu_f(v3);
            }
            if (resid) {
                const float* gp0 = g_mod + (r0 >> 10) * 6 * DIM + gate_chunk * DIM + c0;
                const float* gp1 = g_mod + ((r0 + 8) >> 10) * 6 * DIM + gate_chunk * DIM + c0;
                float2 rr0 = *(const float2*)(resid + (size_t)r0 * N + c0);
                float2 rr1 = *(const float2*)(resid + (size_t)(r0 + 8) * N + c0);
                v0 = rr0.x + gp0[0] * v0;
                v1 = rr0.y + gp0[1] * v1;
                v2 = rr1.x + gp1[0] * v2;
                v3 = rr1.y + gp1[1] * v3;
            }
            if (out_half) {
                __half* Ch = (__half*)C;
                *(uint32_t*)(Ch + (size_t)r0 * N + c0)       = packh2(v0, v1);
                *(uint32_t*)(Ch + (size_t)(r0 + 8) * N + c0) = packh2(v2, v3);
            } else {
                float* Cf = (float*)C;
                *(float2*)(Cf + (size_t)r0 * N + c0)       = make_float2(v0, v1);
                *(float2*)(Cf + (size_t)(r0 + 8) * N + c0) = make_float2(v2, v3);
            }
        }
    }
}

// ============ fused flash attention (fp16 mma, P in registers) ============
#define FP 72
__global__ void __launch_bounds__(128)
flash_kernel()
{
    __shared__ __half Qs[64 * FP];
    __shared__ __half Ks[64 * FP];
    __shared__ __half Vs[64 * FP];

    const int t = threadIdx.x, lane = t & 31, wid = t >> 5;
    const int gid = lane >> 2, tig = lane & 3;
    const int bh = blockIdx.y, b = bh >> 4, h = bh & 15;
    const int q0 = blockIdx.x * 64;
    const int row = wid * 16 + gid;
    const uint32_t vb = (uint32_t)__cvta_generic_to_shared(Vs);

    // load Q tile (half, 8 halves per uint4)
    #pragma unroll
    for (int i = 0; i < 4; i++) {
        int e = (i * 128 + t) * 8;
        int r = e >> 6, c = e & 63;
        *(uint4*)&Qs[r * FP + c] =
            *(const uint4*)(g_qkv + ((size_t)(b * SEQ + q0 + r) * 3) * 1024 + h * 64 + c);
    }

    float m_i[2] = { -1e30f, -1e30f };
    float l_i[2] = { 0.f, 0.f };
    float oacc[8][4];
    #pragma unroll
    for (int ni = 0; ni < 8; ni++)
        #pragma unroll
        for (int q = 0; q < 4; q++) oacc[ni][q] = 0.f;

    for (int kt = 0; kt < SEQ; kt += 64) {
        #pragma unroll
        for (int i = 0; i < 4; i++) {
            int e = (i * 128 + t) * 8;
            int r = e >> 6, c = e & 63;
            *(uint4*)&Ks[r * FP + c] =
                *(const uint4*)(g_qkv + ((size_t)(b * SEQ + kt + r) * 3 + 1) * 1024 + h * 64 + c);
            *(uint4*)&Vs[r * FP + c] =
                *(const uint4*)(g_qkv + ((size_t)(b * SEQ + kt + r) * 3 + 2) * 1024 + h * 64 + c);
        }
        __syncthreads();

        float sacc[8][4];
        #pragma unroll
        for (int ni = 0; ni < 8; ni++)
            #pragma unroll
            for (int q = 0; q < 4; q++) sacc[ni][q] = 0.f;

        #pragma unroll
        for (int ks = 0; ks < 4; ks++) {
            uint32_t af[4];
            af[0] = *(uint32_t*)&Qs[row * FP + ks * 16 + 2 * tig];
            af[1] = *(uint32_t*)&Qs[(row + 8) * FP + ks * 16 + 2 * tig];
            af[2] = *(uint32_t*)&Qs[row * FP + ks * 16 + 8 + 2 * tig];
            af[3] = *(uint32_t*)&Qs[(row + 8) * FP + ks * 16 + 8 + 2 * tig];
            #pragma unroll
            for (int ni = 0; ni < 8; ni++) {
                int n = ni * 8 + gid;
                uint32_t bf[2];
                bf[0] = *(uint32_t*)&Ks[n * FP + ks * 16 + 2 * tig];
                bf[1] = *(uint32_t*)&Ks[n * FP + ks * 16 + 8 + 2 * tig];
                mma16(sacc[ni], af, bf);
            }
        }

        // scale + online softmax
        #pragma unroll
        for (int ni = 0; ni < 8; ni++)
            #pragma unroll
            for (int q = 0; q < 4; q++) sacc[ni][q] *= 0.125f;

        float rmax[2] = { -1e30f, -1e30f };
        #pragma unroll
        for (int ni = 0; ni < 8; ni++) {
            rmax[0] = fmaxf(rmax[0], fmaxf(sacc[ni][0], sacc[ni][1]));
            rmax[1] = fmaxf(rmax[1], fmaxf(sacc[ni][2], sacc[ni][3]));
        }
        #pragma unroll
        for (int w = 1; w <= 2; w <<= 1) {
            rmax[0] = fmaxf(rmax[0], __shfl_xor_sync(0xffffffff, rmax[0], w));
            rmax[1] = fmaxf(rmax[1], __shfl_xor_sync(0xffffffff, rmax[1], w));
        }
        float mnew0 = fmaxf(m_i[0], rmax[0]);
        float mnew1 = fmaxf(m_i[1], rmax[1]);
        float alpha0 = __expf(m_i[0] - mnew0);
        float alpha1 = __expf(m_i[1] - mnew1);
        m_i[0] = mnew0; m_i[1] = mnew1;

        float rsum[2] = { 0.f, 0.f };
        #pragma unroll
        for (int ni = 0; ni < 8; ni++) {
            sacc[ni][0] = __expf(sacc[ni][0] - mnew0);
            sacc[ni][1] = __expf(sacc[ni][1] - mnew0);
            sacc[ni][2] = __expf(sacc[ni][2] - mnew1);
            sacc[ni][3] = __expf(sacc[ni][3] - mnew1);
            rsum[0] += sacc[ni][0] + sacc[ni][1];
            rsum[1] += sacc[ni][2] + sacc[ni][3];
        }
        #pragma unroll
        for (int w = 1; w <= 2; w <<= 1) {
            rsum[0] += __shfl_xor_sync(0xffffffff, rsum[0], w);
            rsum[1] += __shfl_xor_sync(0xffffffff, rsum[1], w);
        }
        l_i[0] = l_i[0] * alpha0 + rsum[0];
        l_i[1] = l_i[1] * alpha1 + rsum[1];

        #pragma unroll
        for (int ni = 0; ni < 8; ni++) {
            oacc[ni][0] *= alpha0; oacc[ni][1] *= alpha0;
            oacc[ni][2] *= alpha1; oacc[ni][3] *= alpha1;
        }

        // O += P @ V  (P straight from registers)
        #pragma unroll
        for (int ks = 0; ks < 4; ks++) {
            uint32_t af[4];
            af[0] = packh2(sacc[2*ks][0],   sacc[2*ks][1]);
            af[1] = packh2(sacc[2*ks][2],   sacc[2*ks][3]);
            af[2] = packh2(sacc[2*ks+1][0], sacc[2*ks+1][1]);
            af[3] = packh2(sacc[2*ks+1][2], sacc[2*ks+1][3]);
            int k = ks * 16 + (lane & 15);
            #pragma unroll
            for (int ni = 0; ni < 8; ni++) {
                uint32_t bf[2];
                ldsm2t(bf, vb + (uint32_t)(k * FP + ni * 8) * 2u);
                mma16(oacc[ni], af, bf);
            }
        }
        __syncthreads();
    }

    float inv0 = __fdividef(1.0f, l_i[0]);
    float inv1 = __fdividef(1.0f, l_i[1]);
    #pragma unroll
    for (int ni = 0; ni < 8; ni++) {
        int c = h * 64 + ni * 8 + tig * 2;
        __half* op0 = g_o + (size_t)(b * SEQ + q0 + row) * 1024 + c;
        __half* op1 = g_o + (size_t)(b * SEQ + q0 + row + 8) * 1024 + c;
        *(uint32_t*)op0 = packh2(oacc[ni][0] * inv0, oacc[ni][1] * inv0);
        *(uint32_t*)op1 = packh2(oacc[ni][2] * inv1, oacc[ni][3] * inv1);
    }
}

// ---------------- adaLN modulation (w_ada read once) ----------------
__global__ void ada_kernel(const float* __restrict__ c,
                           const float* __restrict__ w_ada,
                           const float* __restrict__ b_ada)
{
    int j = blockIdx.x * blockDim.x + threadIdx.x;
    if (j >= 6 * DIM) return;
    float s0 = b_ada[j], s1 = s0, s2 = s0, s3 = s0;
    for (int k = 0; k < DIM; k++) {
        float w = w_ada[k * (6 * DIM) + j];
        s0 += c[k] * w;
        s1 += c[DIM + k] * w;
        s2 += c[2 * DIM + k] * w;
        s3 += c[3 * DIM + k] * w;
    }
    g_mod[j] = s0;
    g_mod[6 * DIM + j] = s1;
    g_mod[12 * DIM + j] = s2;
    g_mod[18 * DIM + j] = s3;
}

// ---------------- LayerNorm + modulate -> half ----------------
__global__ void ln_mod_kernel(const float* __restrict__ x,
                              const float* __restrict__ w,
                              int shift_chunk, int scale_chunk,
                              __half* __restrict__ out)
{
    int row = blockIdx.x;
    int b = row >> 10;
    int t = threadIdx.x;
    const float* xr = x + (size_t)row * DIM;
    float4 v = *(const float4*)(xr + t * 4);
    float sum = v.x + v.y + v.z + v.w;
    float sq  = v.x*v.x + v.y*v.y + v.z*v.z + v.w*v.w;

    __shared__ float s1[256], s2[256];
    s1[t] = sum; s2[t] = sq;
    __syncthreads();
    for (int off = 128; off > 0; off >>= 1) {
        if (t < off) { s1[t] += s1[t + off]; s2[t] += s2[t + off]; }
        __syncthreads();
    }
    float mean = s1[0] * (1.0f / DIM);
    float var  = s2[0] * (1.0f / DIM) - mean * mean;
    float rstd = rsqrtf(var + LN_EPS);

    const float* shiftp = g_mod + b * 6 * DIM + shift_chunk * DIM;
    const float* scalep = g_mod + b * 6 * DIM + scale_chunk * DIM;
    __half* orow = out + (size_t)row * DIM;
    float y[4];
    #pragma unroll
    for (int u = 0; u < 4; u++) {
        int col = t * 4 + u;
        float xv = (u == 0) ? v.x : (u == 1) ? v.y : (u == 2) ? v.z : v.w;
        float yy = (xv - mean) * rstd * w[col];
        y[u] = yy * (1.0f + scalep[col]) + shiftp[col];
    }
    uint2 pk;
    pk.x = packh2(y[0], y[1]);
    pk.y = packh2(y[2], y[3]);
    *(uint2*)(orow + t * 4) = pk;
}

// ---------------- RoPE (half in/out) ----------------
__global__ void rope_kernel(const float* __restrict__ cosb,
                            const float* __restrict__ sinb)
{
    int idx = blockIdx.x * blockDim.x + threadIdx.x;
    if (idx >= BATCH * SEQ * NH * 32) return;
    int i = idx & 31;
    int h = (idx >> 5) & 15;
    int s = (idx >> 9) & 1023;
    int b = idx >> 19;
    float co = cosb[s * 32 + i];
    float si = sinb[s * 32 + i];
    #pragma unroll
    for (int p = 0; p < 2; p++) {
        size_t base = ((((size_t)(b * SEQ + s)) * 3 + p) * NH + h) * HD;
        float t1 = __half2float(g_qkv[base + i]);
        float t2 = __half2float(g_qkv[base + 32 + i]);
        g_qkv[base + i]      = __float2half_rn(t1 * co - t2 * si);
        g_qkv[base + 32 + i] = __float2half_rn(t2 * co + t1 * si);
    }
}

// ---------------- launch ----------------
extern "C" void kernel_launch(void* const* d_in, const int* in_sizes, int n_in,
                              void* d_out, int out_size)
{
    const float* x          = (const float*)d_in[0];
    const float* cosb       = (const float*)d_in[1];
    const float* sinb       = (const float*)d_in[2];
    const float* c          = (const float*)d_in[3];
    const float* w_ln1      = (const float*)d_in[4];
    const float* w_ln2      = (const float*)d_in[5];
    const float* w_qkv      = (const float*)d_in[6];
    const float* w_attn_out = (const float*)d_in[7];
    const float* w_mlp1     = (const float*)d_in[8];
    const float* b_mlp1     = (const float*)d_in[9];
    const float* w_mlp2     = (const float*)d_in[10];
    const float* b_mlp2     = (const float*)d_in[11];
    const float* w_ada      = (const float*)d_in[12];
    const float* b_ada      = (const float*)d_in[13];
    float* out = (float*)d_out;

    __half *p_h, *p_qkv, *p_o, *p_mid, *p_wh;
    float *p_x2;
    cudaGetSymbolAddress((void**)&p_h,   g_h);
    cudaGetSymbolAddress((void**)&p_qkv, g_qkv);
    cudaGetSymbolAddress((void**)&p_o,   g_o);
    cudaGetSymbolAddress((void**)&p_x2,  g_x2);
    cudaGetSymbolAddress((void**)&p_mid, g_mid);
    cudaGetSymbolAddress((void**)&p_wh,  g_wh);

    cudaFuncSetAttribute(tgemm_kernel,
                         cudaFuncAttributeMaxDynamicSharedMemorySize, GSMEM);

    // weight conversions
    cvt_kernel<<<(3*DIM*DIM/8 + 255)/256, 256>>>(w_qkv,      p_wh + WO_QKV,  3*DIM*DIM);
    cvt_kernel<<<(DIM*DIM/8 + 255)/256, 256>>>(w_attn_out,   p_wh + WO_ATTN, DIM*DIM);
    cvt_kernel<<<(DIM*MLP_HID/8 + 255)/256, 256>>>(w_mlp1,   p_wh + WO_MLP1, DIM*MLP_HID);
    cvt_kernel<<<(MLP_HID*DIM/8 + 255)/256, 256>>>(w_mlp2,   p_wh + WO_MLP2, MLP_HID*DIM);

    ada_kernel<<<(6 * DIM + 255) / 256, 256>>>(c, w_ada, b_ada);
    ln_mod_kernel<<<BS, 256>>>(x, w_ln1, 0, 1, p_h);

    tgemm_kernel<<<dim3(3 * DIM / 128, BS / 128), 256, GSMEM>>>(
        p_h, p_wh + WO_QKV, nullptr, nullptr, p_qkv, BS, 3 * DIM, DIM, 0, 0, 1);

    rope_kernel<<<(BATCH * SEQ * NH * 32 + 255) / 256, 256>>>(cosb, sinb);

    flash_kernel<<<dim3(SEQ / 64, BATCH * NH), 128>>>();

    tgemm_kernel<<<dim3(DIM / 128, BS / 128), 256, GSMEM>>>(
        p_o, p_wh + WO_ATTN, nullptr, x, p_x2, BS, DIM, DIM, 0, 2, 0);

    ln_mod_kernel<<<BS, 256>>>(p_x2, w_ln2, 3, 4, p_h);

    tgemm_kernel<<<dim3(MLP_HID / 128, BS / 128), 256, GSMEM>>>(
        p_h, p_wh + WO_MLP1, b_mlp1, nullptr, p_mid, BS, MLP_HID, DIM, 1, 0, 1);

    tgemm_kernel<<<dim3(DIM / 128, BS / 128), 256, GSMEM>>>(
        p_mid, p_wh + WO_MLP2, b_mlp2, p_x2, out, BS, DIM, MLP_HID, 0, 5, 0);
}

// round 7
// speedup vs baseline: 5.6196x; 1.0265x over previous
#include <cuda_runtime.h>
#include <cuda_fp16.h>
#include <math.h>
#include <stdint.h>

#define DIM 1024
#define NH 16
#define HD 64
#define BATCH 4
#define SEQ 1024
#define BS (BATCH*SEQ)
#define MLP_HID 4096
#define LN_EPS 1e-5f

// ---------------- scratch ----------------
__device__ float  g_mod[BATCH * 6 * DIM];
__device__ __half g_h[BS * DIM];
__device__ __half g_qkv[BS * 3 * DIM];
__device__ __half g_o[BS * DIM];
__device__ float  g_x2[BS * DIM];
__device__ __half g_mid[BS * MLP_HID];
#define WO_QKV  0
#define WO_ATTN (3*DIM*DIM)
#define WO_MLP1 (WO_ATTN + DIM*DIM)
#define WO_MLP2 (WO_MLP1 + DIM*MLP_HID)
#define W_TOTAL (WO_MLP2 + MLP_HID*DIM)
__device__ __half g_wh[W_TOTAL];

// ================= helpers =================
__device__ __forceinline__ void mma16(float* c, const uint32_t* a, const uint32_t* b) {
    asm volatile(
        "mma.sync.aligned.m16n8k16.row.col.f32.f16.f16.f32 "
        "{%0,%1,%2,%3}, {%4,%5,%6,%7}, {%8,%9}, {%0,%1,%2,%3};"
        : "+f"(c[0]), "+f"(c[1]), "+f"(c[2]), "+f"(c[3])
        : "r"(a[0]), "r"(a[1]), "r"(a[2]), "r"(a[3]), "r"(b[0]), "r"(b[1]));
}
__device__ __forceinline__ void ldsm4(uint32_t* r, uint32_t addr) {
    asm volatile("ldmatrix.sync.aligned.m8n8.x4.shared.b16 {%0,%1,%2,%3}, [%4];"
        : "=r"(r[0]), "=r"(r[1]), "=r"(r[2]), "=r"(r[3]) : "r"(addr));
}
__device__ __forceinline__ void ldsm4t(uint32_t* r, uint32_t addr) {
    asm volatile("ldmatrix.sync.aligned.m8n8.x4.trans.shared.b16 {%0,%1,%2,%3}, [%4];"
        : "=r"(r[0]), "=r"(r[1]), "=r"(r[2]), "=r"(r[3]) : "r"(addr));
}
__device__ __forceinline__ void ldsm2t(uint32_t* r, uint32_t addr) {
    asm volatile("ldmatrix.sync.aligned.m8n8.x2.trans.shared.b16 {%0,%1}, [%2];"
        : "=r"(r[0]), "=r"(r[1]) : "r"(addr));
}
__device__ __forceinline__ uint32_t packh2(float a, float b) {
    __half2 h = __floats2half2_rn(a, b);
    return *(uint32_t*)&h;
}
__device__ __forceinline__ float gelu_f(float u) {
    float y = 0.7978845608028654f * (u + 0.044715f * u * u * u);
    float e = __expf(2.0f * y);
    return u * (1.0f - __fdividef(1.0f, e + 1.0f));
}

#define CP16(smem, gmem) \
    asm volatile("cp.async.cg.shared.global [%0], [%1], 16;" :: "r"(smem), "l"(gmem))
#define CP_COMMIT() asm volatile("cp.async.commit_group;" ::: "memory")
#define CP_WAIT1()  asm volatile("cp.async.wait_group 1;" ::: "memory")

// ---------------- all weights fp32 -> fp16, one launch ----------------
__global__ void cvt_all_kernel(const float* __restrict__ wqkv,
                               const float* __restrict__ wattn,
                               const float* __restrict__ wmlp1,
                               const float* __restrict__ wmlp2)
{
    int i = (blockIdx.x * blockDim.x + threadIdx.x) * 8;
    if (i >= W_TOTAL) return;
    const float* src;
    int off;
    if (i < WO_ATTN)      { src = wqkv;  off = i; }
    else if (i < WO_MLP1) { src = wattn; off = i - WO_ATTN; }
    else if (i < WO_MLP2) { src = wmlp1; off = i - WO_MLP1; }
    else                  { src = wmlp2; off = i - WO_MLP2; }
    float4 v0 = *(const float4*)(src + off);
    float4 v1 = *(const float4*)(src + off + 4);
    uint4 u;
    u.x = packh2(v0.x, v0.y); u.y = packh2(v0.z, v0.w);
    u.z = packh2(v1.x, v1.y); u.w = packh2(v1.z, v1.w);
    *(uint4*)(g_wh + i) = u;
}

// ============ fp16 mma GEMM, BK=64, 3-stage cp.async ============
// 128x128 CTA tile, 256 threads = 8 warps (2M x 4N), warp tile 64x32.
#define PADA 72        // halves per A row (64 + 8)
#define PADB 136       // halves per B row (128 + 8)
#define ASZH (128 * PADA)
#define BSZH (64 * PADB)
#define STGB ((ASZH + BSZH) * 2)
#define NSTAGE 3
#define GSMEM (NSTAGE * STGB)

__global__ void __launch_bounds__(256)
tgemm_kernel(const __half* __restrict__ A,
             const __half* __restrict__ B,
             const float* __restrict__ bias,
             const float* __restrict__ resid,
             void* __restrict__ C,
             int M, int N, int K, int act, int gate_chunk, int out_half)
{
    extern __shared__ char fsraw[];
    const uint32_t smb = (uint32_t)__cvta_generic_to_shared(fsraw);

    const int t = threadIdx.x, lane = t & 31, wid = t >> 5;
    const int warpM = wid >> 2, warpN = wid & 3;
    const int bm = blockIdx.y * 128, bn = blockIdx.x * 128;
    const int gid = lane >> 2, tig = lane & 3;

    // A fill: 128 rows x 64 halves; 8 halves/thread/iter, 4 iters (32 rows each)
    const int am = (t * 8) >> 6;
    const int ak = (t * 8) & 63;
    // B fill: 64 rows x 128 halves; 4 iters (16 rows each)
    const int bk = (t * 8) >> 7;
    const int bnn = (t * 8) & 127;

    float acc[4][4][4];
    #pragma unroll
    for (int i = 0; i < 4; i++)
        #pragma unroll
        for (int j = 0; j < 4; j++)
            #pragma unroll
            for (int q = 0; q < 4; q++) acc[i][j][q] = 0.f;

    const int NC = K >> 6;

    auto issue = [&](int stage, int kc) {
        uint32_t abase = smb + (uint32_t)(stage * STGB);
        uint32_t bbase = abase + (uint32_t)(ASZH * 2);
        #pragma unroll
        for (int i = 0; i < 4; i++) {
            int m = am + i * 32;
            CP16(abase + (uint32_t)(m * PADA + ak) * 2u,
                 A + (size_t)(bm + m) * K + kc * 64 + ak);
        }
        #pragma unroll
        for (int i = 0; i < 4; i++) {
            int kk = bk + i * 16;
            CP16(bbase + (uint32_t)(kk * PADB + bnn) * 2u,
                 B + (size_t)(kc * 64 + kk) * N + bn + bnn);
        }
    };

    issue(0, 0); CP_COMMIT();
    if (NC > 1) issue(1, 1);
    CP_COMMIT();

    const int arow = warpM * 64 + (lane & 15);
    const int akof = (lane >> 4) * 8;
    const int bkl = lane & 15;
    const int bgof = (lane >> 4) * 8;   // second n8 of the n16 group

    for (int kc = 0; kc < NC; kc++) {
        CP_WAIT1();
        __syncthreads();
        if (kc + 2 < NC) issue((kc + 2) % NSTAGE, kc + 2);
        CP_COMMIT();

        const uint32_t sA = smb + (uint32_t)((kc % NSTAGE) * STGB);
        const uint32_t sB = sA + (uint32_t)(ASZH * 2);

        #pragma unroll
        for (int ks = 0; ks < 4; ks++) {
            uint32_t af[4][4], bf[2][4];
            #pragma unroll
            for (int mi = 0; mi < 4; mi++) {
                int row = arow + mi * 16;
                ldsm4(af[mi], sA + (uint32_t)(row * PADA + ks * 16 + akof) * 2u);
            }
            #pragma unroll
            for (int g = 0; g < 2; g++) {
                int n0 = warpN * 32 + g * 16 + bgof;
                int k = ks * 16 + bkl;
                ldsm4t(bf[g], sB + (uint32_t)(k * PADB + n0) * 2u);
            }
            #pragma unroll
            for (int mi = 0; mi < 4; mi++)
                #pragma unroll
                for (int ni = 0; ni < 4; ni++)
                    mma16(acc[mi][ni], af[mi], &bf[ni >> 1][(ni & 1) * 2]);
        }
    }

    // ---- epilogue ----
    #pragma unroll
    for (int mi = 0; mi < 4; mi++) {
        #pragma unroll
        for (int ni = 0; ni < 4; ni++) {
            int r0 = bm + warpM * 64 + mi * 16 + gid;
            int c0 = bn + warpN * 32 + ni * 8 + tig * 2;
            float v0 = acc[mi][ni][0], v1 = acc[mi][ni][1];
            float v2 = acc[mi][ni][2], v3 = acc[mi][ni][3];
            if (bias) {
                float b0 = bias[c0], b1 = bias[c0 + 1];
                v0 += b0; v1 += b1; v2 += b0; v3 += b1;
            }
            if (act) {
                v0 = gelu_f(v0); v1 = gelu_f(v1);
                v2 = gelu_f(v2); v3 = gelu_f(v3);
            }
            if (resid) {
                const float* gp0 = g_mod + (r0 >> 10) * 6 * DIM + gate_chunk * DIM + c0;
                const float* gp1 = g_mod + ((r0 + 8) >> 10) * 6 * DIM + gate_chunk * DIM + c0;
                float2 rr0 = *(const float2*)(resid + (size_t)r0 * N + c0);
                float2 rr1 = *(const float2*)(resid + (size_t)(r0 + 8) * N + c0);
                v0 = rr0.x + gp0[0] * v0;
                v1 = rr0.y + gp0[1] * v1;
                v2 = rr1.x + gp1[0] * v2;
                v3 = rr1.y + gp1[1] * v3;
            }
            if (out_half) {
                __half* Ch = (__half*)C;
                *(uint32_t*)(Ch + (size_t)r0 * N + c0)       = packh2(v0, v1);
                *(uint32_t*)(Ch + (size_t)(r0 + 8) * N + c0) = packh2(v2, v3);
            } else {
                float* Cf = (float*)C;
                *(float2*)(Cf + (size_t)r0 * N + c0)       = make_float2(v0, v1);
                *(float2*)(Cf + (size_t)(r0 + 8) * N + c0) = make_float2(v2, v3);
            }
        }
    }
}

// ============ fused flash attention (fp16 mma, P in registers) ============
#define FP 72
__global__ void __launch_bounds__(128)
flash_kernel()
{
    __shared__ __half Qs[64 * FP];
    __shared__ __half Ks[64 * FP];
    __shared__ __half Vs[64 * FP];

    const int t = threadIdx.x, lane = t & 31, wid = t >> 5;
    const int gid = lane >> 2, tig = lane & 3;
    const int bh = blockIdx.y, b = bh >> 4, h = bh & 15;
    const int q0 = blockIdx.x * 64;
    const int row = wid * 16 + gid;
    const uint32_t vb = (uint32_t)__cvta_generic_to_shared(Vs);

    #pragma unroll
    for (int i = 0; i < 4; i++) {
        int e = (i * 128 + t) * 8;
        int r = e >> 6, c = e & 63;
        *(uint4*)&Qs[r * FP + c] =
            *(const uint4*)(g_qkv + ((size_t)(b * SEQ + q0 + r) * 3) * 1024 + h * 64 + c);
    }

    float m_i[2] = { -1e30f, -1e30f };
    float l_i[2] = { 0.f, 0.f };
    float oacc[8][4];
    #pragma unroll
    for (int ni = 0; ni < 8; ni++)
        #pragma unroll
        for (int q = 0; q < 4; q++) oacc[ni][q] = 0.f;

    for (int kt = 0; kt < SEQ; kt += 64) {
        #pragma unroll
        for (int i = 0; i < 4; i++) {
            int e = (i * 128 + t) * 8;
            int r = e >> 6, c = e & 63;
            *(uint4*)&Ks[r * FP + c] =
                *(const uint4*)(g_qkv + ((size_t)(b * SEQ + kt + r) * 3 + 1) * 1024 + h * 64 + c);
            *(uint4*)&Vs[r * FP + c] =
                *(const uint4*)(g_qkv + ((size_t)(b * SEQ + kt + r) * 3 + 2) * 1024 + h * 64 + c);
        }
        __syncthreads();

        float sacc[8][4];
        #pragma unroll
        for (int ni = 0; ni < 8; ni++)
            #pragma unroll
            for (int q = 0; q < 4; q++) sacc[ni][q] = 0.f;

        #pragma unroll
        for (int ks = 0; ks < 4; ks++) {
            uint32_t af[4];
            af[0] = *(uint32_t*)&Qs[row * FP + ks * 16 + 2 * tig];
            af[1] = *(uint32_t*)&Qs[(row + 8) * FP + ks * 16 + 2 * tig];
            af[2] = *(uint32_t*)&Qs[row * FP + ks * 16 + 8 + 2 * tig];
            af[3] = *(uint32_t*)&Qs[(row + 8) * FP + ks * 16 + 8 + 2 * tig];
            #pragma unroll
            for (int ni = 0; ni < 8; ni++) {
                int n = ni * 8 + gid;
                uint32_t bf[2];
                bf[0] = *(uint32_t*)&Ks[n * FP + ks * 16 + 2 * tig];
                bf[1] = *(uint32_t*)&Ks[n * FP + ks * 16 + 8 + 2 * tig];
                mma16(sacc[ni], af, bf);
            }
        }

        #pragma unroll
        for (int ni = 0; ni < 8; ni++)
            #pragma unroll
            for (int q = 0; q < 4; q++) sacc[ni][q] *= 0.125f;

        float rmax[2] = { -1e30f, -1e30f };
        #pragma unroll
        for (int ni = 0; ni < 8; ni++) {
            rmax[0] = fmaxf(rmax[0], fmaxf(sacc[ni][0], sacc[ni][1]));
            rmax[1] = fmaxf(rmax[1], fmaxf(sacc[ni][2], sacc[ni][3]));
        }
        #pragma unroll
        for (int w = 1; w <= 2; w <<= 1) {
            rmax[0] = fmaxf(rmax[0], __shfl_xor_sync(0xffffffff, rmax[0], w));
            rmax[1] = fmaxf(rmax[1], __shfl_xor_sync(0xffffffff, rmax[1], w));
        }
        float mnew0 = fmaxf(m_i[0], rmax[0]);
        float mnew1 = fmaxf(m_i[1], rmax[1]);
        float alpha0 = __expf(m_i[0] - mnew0);
        float alpha1 = __expf(m_i[1] - mnew1);
        m_i[0] = mnew0; m_i[1] = mnew1;

        float rsum[2] = { 0.f, 0.f };
        #pragma unroll
        for (int ni = 0; ni < 8; ni++) {
            sacc[ni][0] = __expf(sacc[ni][0] - mnew0);
            sacc[ni][1] = __expf(sacc[ni][1] - mnew0);
            sacc[ni][2] = __expf(sacc[ni][2] - mnew1);
            sacc[ni][3] = __expf(sacc[ni][3] - mnew1);
            rsum[0] += sacc[ni][0] + sacc[ni][1];
            rsum[1] += sacc[ni][2] + sacc[ni][3];
        }
        #pragma unroll
        for (int w = 1; w <= 2; w <<= 1) {
            rsum[0] += __shfl_xor_sync(0xffffffff, rsum[0], w);
            rsum[1] += __shfl_xor_sync(0xffffffff, rsum[1], w);
        }
        l_i[0] = l_i[0] * alpha0 + rsum[0];
        l_i[1] = l_i[1] * alpha1 + rsum[1];

        #pragma unroll
        for (int ni = 0; ni < 8; ni++) {
            oacc[ni][0] *= alpha0; oacc[ni][1] *= alpha0;
            oacc[ni][2] *= alpha1; oacc[ni][3] *= alpha1;
        }

        #pragma unroll
        for (int ks = 0; ks < 4; ks++) {
            uint32_t af[4];
            af[0] = packh2(sacc[2*ks][0],   sacc[2*ks][1]);
            af[1] = packh2(sacc[2*ks][2],   sacc[2*ks][3]);
            af[2] = packh2(sacc[2*ks+1][0], sacc[2*ks+1][1]);
            af[3] = packh2(sacc[2*ks+1][2], sacc[2*ks+1][3]);
            int k = ks * 16 + (lane & 15);
            #pragma unroll
            for (int ni = 0; ni < 8; ni++) {
                uint32_t bf[2];
                ldsm2t(bf, vb + (uint32_t)(k * FP + ni * 8) * 2u);
                mma16(oacc[ni], af, bf);
            }
        }
        __syncthreads();
    }

    float inv0 = __fdividef(1.0f, l_i[0]);
    float inv1 = __fdividef(1.0f, l_i[1]);
    #pragma unroll
    for (int ni = 0; ni < 8; ni++) {
        int c = h * 64 + ni * 8 + tig * 2;
        __half* op0 = g_o + (size_t)(b * SEQ + q0 + row) * 1024 + c;
        __half* op1 = g_o + (size_t)(b * SEQ + q0 + row + 8) * 1024 + c;
        *(uint32_t*)op0 = packh2(oacc[ni][0] * inv0, oacc[ni][1] * inv0);
        *(uint32_t*)op1 = packh2(oacc[ni][2] * inv1, oacc[ni][3] * inv1);
    }
}

// ---------------- adaLN modulation ----------------
__global__ void ada_kernel(const float* __restrict__ c,
                           const float* __restrict__ w_ada,
                           const float* __restrict__ b_ada)
{
    int j = blockIdx.x * blockDim.x + threadIdx.x;
    if (j >= 6 * DIM) return;
    float s0 = b_ada[j], s1 = s0, s2 = s0, s3 = s0;
    for (int k = 0; k < DIM; k++) {
        float w = w_ada[k * (6 * DIM) + j];
        s0 += c[k] * w;
        s1 += c[DIM + k] * w;
        s2 += c[2 * DIM + k] * w;
        s3 += c[3 * DIM + k] * w;
    }
    g_mod[j] = s0;
    g_mod[6 * DIM + j] = s1;
    g_mod[12 * DIM + j] = s2;
    g_mod[18 * DIM + j] = s3;
}

// ---------------- LayerNorm + modulate -> half ----------------
__global__ void ln_mod_kernel(const float* __restrict__ x,
                              const float* __restrict__ w,
                              int shift_chunk, int scale_chunk,
                              __half* __restrict__ out)
{
    int row = blockIdx.x;
    int b = row >> 10;
    int t = threadIdx.x;
    const float* xr = x + (size_t)row * DIM;
    float4 v = *(const float4*)(xr + t * 4);
    float sum = v.x + v.y + v.z + v.w;
    float sq  = v.x*v.x + v.y*v.y + v.z*v.z + v.w*v.w;

    __shared__ float s1[256], s2[256];
    s1[t] = sum; s2[t] = sq;
    __syncthreads();
    for (int off = 128; off > 0; off >>= 1) {
        if (t < off) { s1[t] += s1[t + off]; s2[t] += s2[t + off]; }
        __syncthreads();
    }
    float mean = s1[0] * (1.0f / DIM);
    float var  = s2[0] * (1.0f / DIM) - mean * mean;
    float rstd = rsqrtf(var + LN_EPS);

    const float* shiftp = g_mod + b * 6 * DIM + shift_chunk * DIM;
    const float* scalep = g_mod + b * 6 * DIM + scale_chunk * DIM;
    __half* orow = out + (size_t)row * DIM;
    float y[4];
    #pragma unroll
    for (int u = 0; u < 4; u++) {
        int col = t * 4 + u;
        float xv = (u == 0) ? v.x : (u == 1) ? v.y : (u == 2) ? v.z : v.w;
        float yy = (xv - mean) * rstd * w[col];
        y[u] = yy * (1.0f + scalep[col]) + shiftp[col];
    }
    uint2 pk;
    pk.x = packh2(y[0], y[1]);
    pk.y = packh2(y[2], y[3]);
    *(uint2*)(orow + t * 4) = pk;
}

// ---------------- RoPE (half in/out) ----------------
__global__ void rope_kernel(const float* __restrict__ cosb,
                            const float* __restrict__ sinb)
{
    int idx = blockIdx.x * blockDim.x + threadIdx.x;
    if (idx >= BATCH * SEQ * NH * 32) return;
    int i = idx & 31;
    int h = (idx >> 5) & 15;
    int s = (idx >> 9) & 1023;
    int b = idx >> 19;
    float co = cosb[s * 32 + i];
    float si = sinb[s * 32 + i];
    #pragma unroll
    for (int p = 0; p < 2; p++) {
        size_t base = ((((size_t)(b * SEQ + s)) * 3 + p) * NH + h) * HD;
        float t1 = __half2float(g_qkv[base + i]);
        float t2 = __half2float(g_qkv[base + 32 + i]);
        g_qkv[base + i]      = __float2half_rn(t1 * co - t2 * si);
        g_qkv[base + 32 + i] = __float2half_rn(t2 * co + t1 * si);
    }
}

// ---------------- launch ----------------
extern "C" void kernel_launch(void* const* d_in, const int* in_sizes, int n_in,
                              void* d_out, int out_size)
{
    const float* x          = (const float*)d_in[0];
    const float* cosb       = (const float*)d_in[1];
    const float* sinb       = (const float*)d_in[2];
    const float* c          = (const float*)d_in[3];
    const float* w_ln1      = (const float*)d_in[4];
    const float* w_ln2      = (const float*)d_in[5];
    const float* w_qkv      = (const float*)d_in[6];
    const float* w_attn_out = (const float*)d_in[7];
    const float* w_mlp1     = (const float*)d_in[8];
    const float* b_mlp1     = (const float*)d_in[9];
    const float* w_mlp2     = (const float*)d_in[10];
    const float* b_mlp2     = (const float*)d_in[11];
    const float* w_ada      = (const float*)d_in[12];
    const float* b_ada      = (const float*)d_in[13];
    float* out = (float*)d_out;

    __half *p_h, *p_qkv, *p_o, *p_mid, *p_wh;
    float *p_x2;
    cudaGetSymbolAddress((void**)&p_h,   g_h);
    cudaGetSymbolAddress((void**)&p_qkv, g_qkv);
    cudaGetSymbolAddress((void**)&p_o,   g_o);
    cudaGetSymbolAddress((void**)&p_x2,  g_x2);
    cudaGetSymbolAddress((void**)&p_mid, g_mid);
    cudaGetSymbolAddress((void**)&p_wh,  g_wh);

    cudaFuncSetAttribute(tgemm_kernel,
                         cudaFuncAttributeMaxDynamicSharedMemorySize, GSMEM);

    cvt_all_kernel<<<(W_TOTAL/8 + 255)/256, 256>>>(w_qkv, w_attn_out, w_mlp1, w_mlp2);

    ada_kernel<<<(6 * DIM + 255) / 256, 256>>>(c, w_ada, b_ada);
    ln_mod_kernel<<<BS, 256>>>(x, w_ln1, 0, 1, p_h);

    tgemm_kernel<<<dim3(3 * DIM / 128, BS / 128), 256, GSMEM>>>(
        p_h, p_wh + WO_QKV, nullptr, nullptr, p_qkv, BS, 3 * DIM, DIM, 0, 0, 1);

    rope_kernel<<<(BATCH * SEQ * NH * 32 + 255) / 256, 256>>>(cosb, sinb);

    flash_kernel<<<dim3(SEQ / 64, BATCH * NH), 128>>>();

    tgemm_kernel<<<dim3(DIM / 128, BS / 128), 256, GSMEM>>>(
        p_o, p_wh + WO_ATTN, nullptr, x, p_x2, BS, DIM, DIM, 0, 2, 0);

    ln_mod_kernel<<<BS, 256>>>(p_x2, w_ln2, 3, 4, p_h);

    tgemm_kernel<<<dim3(MLP_HID / 128, BS / 128), 256, GSMEM>>>(
        p_h, p_wh + WO_MLP1, b_mlp1, nullptr, p_mid, BS, MLP_HID, DIM, 1, 0, 1);

    tgemm_kernel<<<dim3(DIM / 128, BS / 128), 256, GSMEM>>>(
        p_mid, p_wh + WO_MLP2, b_mlp2, p_x2, out, BS, DIM, MLP_HID, 0, 5, 0);
}

// round 8
// speedup vs baseline: 5.6646x; 1.0080x over previous
#include <cuda_runtime.h>
#include <cuda_fp16.h>
#include <math.h>
#include <stdint.h>

#define DIM 1024
#define NH 16
#define HD 64
#define BATCH 4
#define SEQ 1024
#define BS (BATCH*SEQ)
#define MLP_HID 4096
#define LN_EPS 1e-5f

// ---------------- scratch ----------------
__device__ float  g_mod[BATCH * 6 * DIM];
__device__ __half g_h[BS * DIM];
__device__ __half g_qkv[BS * 3 * DIM];
__device__ __half g_o[BS * DIM];
__device__ float  g_x2[BS * DIM];
__device__ __half g_mid[BS * MLP_HID];
#define WO_QKV  0
#define WO_ATTN (3*DIM*DIM)
#define WO_MLP1 (WO_ATTN + DIM*DIM)
#define WO_MLP2 (WO_MLP1 + DIM*MLP_HID)
#define W_TOTAL (WO_MLP2 + MLP_HID*DIM)
__device__ __half g_wh[W_TOTAL];

// ================= helpers =================
__device__ __forceinline__ void mma16(float* c, const uint32_t* a, const uint32_t* b) {
    asm volatile(
        "mma.sync.aligned.m16n8k16.row.col.f32.f16.f16.f32 "
        "{%0,%1,%2,%3}, {%4,%5,%6,%7}, {%8,%9}, {%0,%1,%2,%3};"
        : "+f"(c[0]), "+f"(c[1]), "+f"(c[2]), "+f"(c[3])
        : "r"(a[0]), "r"(a[1]), "r"(a[2]), "r"(a[3]), "r"(b[0]), "r"(b[1]));
}
__device__ __forceinline__ void ldsm4(uint32_t* r, uint32_t addr) {
    asm volatile("ldmatrix.sync.aligned.m8n8.x4.shared.b16 {%0,%1,%2,%3}, [%4];"
        : "=r"(r[0]), "=r"(r[1]), "=r"(r[2]), "=r"(r[3]) : "r"(addr));
}
__device__ __forceinline__ void ldsm4t(uint32_t* r, uint32_t addr) {
    asm volatile("ldmatrix.sync.aligned.m8n8.x4.trans.shared.b16 {%0,%1,%2,%3}, [%4];"
        : "=r"(r[0]), "=r"(r[1]), "=r"(r[2]), "=r"(r[3]) : "r"(addr));
}
__device__ __forceinline__ void ldsm2t(uint32_t* r, uint32_t addr) {
    asm volatile("ldmatrix.sync.aligned.m8n8.x2.trans.shared.b16 {%0,%1}, [%2];"
        : "=r"(r[0]), "=r"(r[1]) : "r"(addr));
}
__device__ __forceinline__ uint32_t packh2(float a, float b) {
    __half2 h = __floats2half2_rn(a, b);
    return *(uint32_t*)&h;
}
__device__ __forceinline__ float gelu_f(float u) {
    float y = 0.7978845608028654f * (u + 0.044715f * u * u * u);
    float e = __expf(2.0f * y);
    return u * (1.0f - __fdividef(1.0f, e + 1.0f));
}

#define CP16(smem, gmem) \
    asm volatile("cp.async.cg.shared.global [%0], [%1], 16;" :: "r"(smem), "l"(gmem))
#define CP_COMMIT() asm volatile("cp.async.commit_group;" ::: "memory")
#define CP_WAIT1()  asm volatile("cp.async.wait_group 1;" ::: "memory")

// ---------------- all weights fp32 -> fp16, one launch ----------------
__global__ void cvt_all_kernel(const float* __restrict__ wqkv,
                               const float* __restrict__ wattn,
                               const float* __restrict__ wmlp1,
                               const float* __restrict__ wmlp2)
{
    int i = (blockIdx.x * blockDim.x + threadIdx.x) * 8;
    if (i >= W_TOTAL) return;
    const float* src;
    int off;
    if (i < WO_ATTN)      { src = wqkv;  off = i; }
    else if (i < WO_MLP1) { src = wattn; off = i - WO_ATTN; }
    else if (i < WO_MLP2) { src = wmlp1; off = i - WO_MLP1; }
    else                  { src = wmlp2; off = i - WO_MLP2; }
    float4 v0 = *(const float4*)(src + off);
    float4 v1 = *(const float4*)(src + off + 4);
    uint4 u;
    u.x = packh2(v0.x, v0.y); u.y = packh2(v0.z, v0.w);
    u.z = packh2(v1.x, v1.y); u.w = packh2(v1.z, v1.w);
    *(uint4*)(g_wh + i) = u;
}

// ============ fp16 mma GEMM, BK=64, 2-stage cp.async, 2 CTA/SM ============
// 128x128 CTA tile, 256 threads = 8 warps (2M x 4N), warp tile 64x32.
#define PADA 72        // halves per A row (64 + 8)
#define PADB 136       // halves per B row (128 + 8)
#define ASZH (128 * PADA)
#define BSZH (64 * PADB)
#define STGB ((ASZH + BSZH) * 2)
#define NSTAGE 2
#define GSMEM (NSTAGE * STGB)

__global__ void __launch_bounds__(256, 2)
tgemm_kernel(const __half* __restrict__ A,
             const __half* __restrict__ B,
             const float* __restrict__ bias,
             const float* __restrict__ resid,
             void* __restrict__ C,
             int M, int N, int K, int act, int gate_chunk, int out_half)
{
    extern __shared__ char fsraw[];
    const uint32_t smb = (uint32_t)__cvta_generic_to_shared(fsraw);

    const int t = threadIdx.x, lane = t & 31, wid = t >> 5;
    const int warpM = wid >> 2, warpN = wid & 3;
    const int bm = blockIdx.y * 128, bn = blockIdx.x * 128;
    const int gid = lane >> 2, tig = lane & 3;

    const int am = (t * 8) >> 6;
    const int ak = (t * 8) & 63;
    const int bk = (t * 8) >> 7;
    const int bnn = (t * 8) & 127;

    float acc[4][4][4];
    #pragma unroll
    for (int i = 0; i < 4; i++)
        #pragma unroll
        for (int j = 0; j < 4; j++)
            #pragma unroll
            for (int q = 0; q < 4; q++) acc[i][j][q] = 0.f;

    const int NC = K >> 6;

    auto issue = [&](int stage, int kc) {
        uint32_t abase = smb + (uint32_t)(stage * STGB);
        uint32_t bbase = abase + (uint32_t)(ASZH * 2);
        #pragma unroll
        for (int i = 0; i < 4; i++) {
            int m = am + i * 32;
            CP16(abase + (uint32_t)(m * PADA + ak) * 2u,
                 A + (size_t)(bm + m) * K + kc * 64 + ak);
        }
        #pragma unroll
        for (int i = 0; i < 4; i++) {
            int kk = bk + i * 16;
            CP16(bbase + (uint32_t)(kk * PADB + bnn) * 2u,
                 B + (size_t)(kc * 64 + kk) * N + bn + bnn);
        }
    };

    issue(0, 0); CP_COMMIT();
    if (NC > 1) issue(1, 1);
    CP_COMMIT();

    const int arow = warpM * 64 + (lane & 15);
    const int akof = (lane >> 4) * 8;
    const int bkl = lane & 15;
    const int bgof = (lane >> 4) * 8;

    for (int kc = 0; kc < NC; kc++) {
        CP_WAIT1();
        __syncthreads();

        const uint32_t sA = smb + (uint32_t)((kc & 1) * STGB);
        const uint32_t sB = sA + (uint32_t)(ASZH * 2);

        #pragma unroll
        for (int ks = 0; ks < 4; ks++) {
            uint32_t af[4][4], bf[2][4];
            #pragma unroll
            for (int mi = 0; mi < 4; mi++) {
                int row = arow + mi * 16;
                ldsm4(af[mi], sA + (uint32_t)(row * PADA + ks * 16 + akof) * 2u);
            }
            #pragma unroll
            for (int g = 0; g < 2; g++) {
                int n0 = warpN * 32 + g * 16 + bgof;
                int k = ks * 16 + bkl;
                ldsm4t(bf[g], sB + (uint32_t)(k * PADB + n0) * 2u);
            }
            #pragma unroll
            for (int mi = 0; mi < 4; mi++)
                #pragma unroll
                for (int ni = 0; ni < 4; ni++)
                    mma16(acc[mi][ni], af[mi], &bf[ni >> 1][(ni & 1) * 2]);
        }

        // buffer (kc&1) free only after ALL warps finished reading it
        if (kc + 2 < NC) {
            __syncthreads();
            issue(kc & 1, kc + 2);
        }
        CP_COMMIT();
    }

    // ---- epilogue ----
    #pragma unroll
    for (int mi = 0; mi < 4; mi++) {
        #pragma unroll
        for (int ni = 0; ni < 4; ni++) {
            int r0 = bm + warpM * 64 + mi * 16 + gid;
            int c0 = bn + warpN * 32 + ni * 8 + tig * 2;
            float v0 = acc[mi][ni][0], v1 = acc[mi][ni][1];
            float v2 = acc[mi][ni][2], v3 = acc[mi][ni][3];
            if (bias) {
                float b0 = bias[c0], b1 = bias[c0 + 1];
                v0 += b0; v1 += b1; v2 += b0; v3 += b1;
            }
            if (act) {
                v0 = gelu_f(v0); v1 = gelu_f(v1);
                v2 = gelu_f(v2); v3 = gelu_f(v3);
            }
            if (resid) {
                const float* gp0 = g_mod + (r0 >> 10) * 6 * DIM + gate_chunk * DIM + c0;
                const float* gp1 = g_mod + ((r0 + 8) >> 10) * 6 * DIM + gate_chunk * DIM + c0;
                float2 rr0 = *(const float2*)(resid + (size_t)r0 * N + c0);
                float2 rr1 = *(const float2*)(resid + (size_t)(r0 + 8) * N + c0);
                v0 = rr0.x + gp0[0] * v0;
                v1 = rr0.y + gp0[1] * v1;
                v2 = rr1.x + gp1[0] * v2;
                v3 = rr1.y + gp1[1] * v3;
            }
            if (out_half) {
                __half* Ch = (__half*)C;
                *(uint32_t*)(Ch + (size_t)r0 * N + c0)       = packh2(v0, v1);
                *(uint32_t*)(Ch + (size_t)(r0 + 8) * N + c0) = packh2(v2, v3);
            } else {
                float* Cf = (float*)C;
                *(float2*)(Cf + (size_t)r0 * N + c0)       = make_float2(v0, v1);
                *(float2*)(Cf + (size_t)(r0 + 8) * N + c0) = make_float2(v2, v3);
            }
        }
    }
}

// ============ fused flash attention (fp16 mma, P in registers) ============
#define FP 72
__global__ void __launch_bounds__(128)
flash_kernel()
{
    __shared__ __half Qs[64 * FP];
    __shared__ __half Ks[64 * FP];
    __shared__ __half Vs[64 * FP];

    const int t = threadIdx.x, lane = t & 31, wid = t >> 5;
    const int gid = lane >> 2, tig = lane & 3;
    const int bh = blockIdx.y, b = bh >> 4, h = bh & 15;
    const int q0 = blockIdx.x * 64;
    const int row = wid * 16 + gid;
    const uint32_t vb = (uint32_t)__cvta_generic_to_shared(Vs);

    #pragma unroll
    for (int i = 0; i < 4; i++) {
        int e = (i * 128 + t) * 8;
        int r = e >> 6, c = e & 63;
        *(uint4*)&Qs[r * FP + c] =
            *(const uint4*)(g_qkv + ((size_t)(b * SEQ + q0 + r) * 3) * 1024 + h * 64 + c);
    }

    float m_i[2] = { -1e30f, -1e30f };
    float l_i[2] = { 0.f, 0.f };
    float oacc[8][4];
    #pragma unroll
    for (int ni = 0; ni < 8; ni++)
        #pragma unroll
        for (int q = 0; q < 4; q++) oacc[ni][q] = 0.f;

    for (int kt = 0; kt < SEQ; kt += 64) {
        #pragma unroll
        for (int i = 0; i < 4; i++) {
            int e = (i * 128 + t) * 8;
            int r = e >> 6, c = e & 63;
            *(uint4*)&Ks[r * FP + c] =
                *(const uint4*)(g_qkv + ((size_t)(b * SEQ + kt + r) * 3 + 1) * 1024 + h * 64 + c);
            *(uint4*)&Vs[r * FP + c] =
                *(const uint4*)(g_qkv + ((size_t)(b * SEQ + kt + r) * 3 + 2) * 1024 + h * 64 + c);
        }
        __syncthreads();

        float sacc[8][4];
        #pragma unroll
        for (int ni = 0; ni < 8; ni++)
            #pragma unroll
            for (int q = 0; q < 4; q++) sacc[ni][q] = 0.f;

        #pragma unroll
        for (int ks = 0; ks < 4; ks++) {
            uint32_t af[4];
            af[0] = *(uint32_t*)&Qs[row * FP + ks * 16 + 2 * tig];
            af[1] = *(uint32_t*)&Qs[(row + 8) * FP + ks * 16 + 2 * tig];
            af[2] = *(uint32_t*)&Qs[row * FP + ks * 16 + 8 + 2 * tig];
            af[3] = *(uint32_t*)&Qs[(row + 8) * FP + ks * 16 + 8 + 2 * tig];
            #pragma unroll
            for (int ni = 0; ni < 8; ni++) {
                int n = ni * 8 + gid;
                uint32_t bf[2];
                bf[0] = *(uint32_t*)&Ks[n * FP + ks * 16 + 2 * tig];
                bf[1] = *(uint32_t*)&Ks[n * FP + ks * 16 + 8 + 2 * tig];
                mma16(sacc[ni], af, bf);
            }
        }

        #pragma unroll
        for (int ni = 0; ni < 8; ni++)
            #pragma unroll
            for (int q = 0; q < 4; q++) sacc[ni][q] *= 0.125f;

        float rmax[2] = { -1e30f, -1e30f };
        #pragma unroll
        for (int ni = 0; ni < 8; ni++) {
            rmax[0] = fmaxf(rmax[0], fmaxf(sacc[ni][0], sacc[ni][1]));
            rmax[1] = fmaxf(rmax[1], fmaxf(sacc[ni][2], sacc[ni][3]));
        }
        #pragma unroll
        for (int w = 1; w <= 2; w <<= 1) {
            rmax[0] = fmaxf(rmax[0], __shfl_xor_sync(0xffffffff, rmax[0], w));
            rmax[1] = fmaxf(rmax[1], __shfl_xor_sync(0xffffffff, rmax[1], w));
        }
        float mnew0 = fmaxf(m_i[0], rmax[0]);
        float mnew1 = fmaxf(m_i[1], rmax[1]);
        float alpha0 = __expf(m_i[0] - mnew0);
        float alpha1 = __expf(m_i[1] - mnew1);
        m_i[0] = mnew0; m_i[1] = mnew1;

        float rsum[2] = { 0.f, 0.f };
        #pragma unroll
        for (int ni = 0; ni < 8; ni++) {
            sacc[ni][0] = __expf(sacc[ni][0] - mnew0);
            sacc[ni][1] = __expf(sacc[ni][1] - mnew0);
            sacc[ni][2] = __expf(sacc[ni][2] - mnew1);
            sacc[ni][3] = __expf(sacc[ni][3] - mnew1);
            rsum[0] += sacc[ni][0] + sacc[ni][1];
            rsum[1] += sacc[ni][2] + sacc[ni][3];
        }
        #pragma unroll
        for (int w = 1; w <= 2; w <<= 1) {
            rsum[0] += __shfl_xor_sync(0xffffffff, rsum[0], w);
            rsum[1] += __shfl_xor_sync(0xffffffff, rsum[1], w);
        }
        l_i[0] = l_i[0] * alpha0 + rsum[0];
        l_i[1] = l_i[1] * alpha1 + rsum[1];

        #pragma unroll
        for (int ni = 0; ni < 8; ni++) {
            oacc[ni][0] *= alpha0; oacc[ni][1] *= alpha0;
            oacc[ni][2] *= alpha1; oacc[ni][3] *= alpha1;
        }

        #pragma unroll
        for (int ks = 0; ks < 4; ks++) {
            uint32_t af[4];
            af[0] = packh2(sacc[2*ks][0],   sacc[2*ks][1]);
            af[1] = packh2(sacc[2*ks][2],   sacc[2*ks][3]);
            af[2] = packh2(sacc[2*ks+1][0], sacc[2*ks+1][1]);
            af[3] = packh2(sacc[2*ks+1][2], sacc[2*ks+1][3]);
            int k = ks * 16 + (lane & 15);
            #pragma unroll
            for (int ni = 0; ni < 8; ni++) {
                uint32_t bf[2];
                ldsm2t(bf, vb + (uint32_t)(k * FP + ni * 8) * 2u);
                mma16(oacc[ni], af, bf);
            }
        }
        __syncthreads();
    }

    float inv0 = __fdividef(1.0f, l_i[0]);
    float inv1 = __fdividef(1.0f, l_i[1]);
    #pragma unroll
    for (int ni = 0; ni < 8; ni++) {
        int c = h * 64 + ni * 8 + tig * 2;
        __half* op0 = g_o + (size_t)(b * SEQ + q0 + row) * 1024 + c;
        __half* op1 = g_o + (size_t)(b * SEQ + q0 + row + 8) * 1024 + c;
        *(uint32_t*)op0 = packh2(oacc[ni][0] * inv0, oacc[ni][1] * inv0);
        *(uint32_t*)op1 = packh2(oacc[ni][2] * inv1, oacc[ni][3] * inv1);
    }
}

// ---------------- adaLN modulation ----------------
__global__ void ada_kernel(const float* __restrict__ c,
                           const float* __restrict__ w_ada,
                           const float* __restrict__ b_ada)
{
    int j = blockIdx.x * blockDim.x + threadIdx.x;
    if (j >= 6 * DIM) return;
    float s0 = b_ada[j], s1 = s0, s2 = s0, s3 = s0;
    for (int k = 0; k < DIM; k++) {
        float w = w_ada[k * (6 * DIM) + j];
        s0 += c[k] * w;
        s1 += c[DIM + k] * w;
        s2 += c[2 * DIM + k] * w;
        s3 += c[3 * DIM + k] * w;
    }
    g_mod[j] = s0;
    g_mod[6 * DIM + j] = s1;
    g_mod[12 * DIM + j] = s2;
    g_mod[18 * DIM + j] = s3;
}

// ---------------- LayerNorm + modulate -> half ----------------
__global__ void ln_mod_kernel(const float* __restrict__ x,
                              const float* __restrict__ w,
                              int shift_chunk, int scale_chunk,
                              __half* __restrict__ out)
{
    int row = blockIdx.x;
    int b = row >> 10;
    int t = threadIdx.x;
    const float* xr = x + (size_t)row * DIM;
    float4 v = *(const float4*)(xr + t * 4);
    float sum = v.x + v.y + v.z + v.w;
    float sq  = v.x*v.x + v.y*v.y + v.z*v.z + v.w*v.w;

    __shared__ float s1[256], s2[256];
    s1[t] = sum; s2[t] = sq;
    __syncthreads();
    for (int off = 128; off > 0; off >>= 1) {
        if (t < off) { s1[t] += s1[t + off]; s2[t] += s2[t + off]; }
        __syncthreads();
    }
    float mean = s1[0] * (1.0f / DIM);
    float var  = s2[0] * (1.0f / DIM) - mean * mean;
    float rstd = rsqrtf(var + LN_EPS);

    const float* shiftp = g_mod + b * 6 * DIM + shift_chunk * DIM;
    const float* scalep = g_mod + b * 6 * DIM + scale_chunk * DIM;
    __half* orow = out + (size_t)row * DIM;
    float y[4];
    #pragma unroll
    for (int u = 0; u < 4; u++) {
        int col = t * 4 + u;
        float xv = (u == 0) ? v.x : (u == 1) ? v.y : (u == 2) ? v.z : v.w;
        float yy = (xv - mean) * rstd * w[col];
        y[u] = yy * (1.0f + scalep[col]) + shiftp[col];
    }
    uint2 pk;
    pk.x = packh2(y[0], y[1]);
    pk.y = packh2(y[2], y[3]);
    *(uint2*)(orow + t * 4) = pk;
}

// ---------------- RoPE (half in/out) ----------------
__global__ void rope_kernel(const float* __restrict__ cosb,
                            const float* __restrict__ sinb)
{
    int idx = blockIdx.x * blockDim.x + threadIdx.x;
    if (idx >= BATCH * SEQ * NH * 32) return;
    int i = idx & 31;
    int h = (idx >> 5) & 15;
    int s = (idx >> 9) & 1023;
    int b = idx >> 19;
    float co = cosb[s * 32 + i];
    float si = sinb[s * 32 + i];
    #pragma unroll
    for (int p = 0; p < 2; p++) {
        size_t base = ((((size_t)(b * SEQ + s)) * 3 + p) * NH + h) * HD;
        float t1 = __half2float(g_qkv[base + i]);
        float t2 = __half2float(g_qkv[base + 32 + i]);
        g_qkv[base + i]      = __float2half_rn(t1 * co - t2 * si);
        g_qkv[base + 32 + i] = __float2half_rn(t2 * co + t1 * si);
    }
}

// ---------------- launch ----------------
extern "C" void kernel_launch(void* const* d_in, const int* in_sizes, int n_in,
                              void* d_out, int out_size)
{
    const float* x          = (const float*)d_in[0];
    const float* cosb       = (const float*)d_in[1];
    const float* sinb       = (const float*)d_in[2];
    const float* c          = (const float*)d_in[3];
    const float* w_ln1      = (const float*)d_in[4];
    const float* w_ln2      = (const float*)d_in[5];
    const float* w_qkv      = (const float*)d_in[6];
    const float* w_attn_out = (const float*)d_in[7];
    const float* w_mlp1     = (const float*)d_in[8];
    const float* b_mlp1     = (const float*)d_in[9];
    const float* w_mlp2     = (const float*)d_in[10];
    const float* b_mlp2     = (const float*)d_in[11];
    const float* w_ada      = (const float*)d_in[12];
    const float* b_ada      = (const float*)d_in[13];
    float* out = (float*)d_out;

    __half *p_h, *p_qkv, *p_o, *p_mid, *p_wh;
    float *p_x2;
    cudaGetSymbolAddress((void**)&p_h,   g_h);
    cudaGetSymbolAddress((void**)&p_qkv, g_qkv);
    cudaGetSymbolAddress((void**)&p_o,   g_o);
    cudaGetSymbolAddress((void**)&p_x2,  g_x2);
    cudaGetSymbolAddress((void**)&p_mid, g_mid);
    cudaGetSymbolAddress((void**)&p_wh,  g_wh);

    cudaFuncSetAttribute(tgemm_kernel,
                         cudaFuncAttributeMaxDynamicSharedMemorySize, GSMEM);

    cvt_all_kernel<<<(W_TOTAL/8 + 255)/256, 256>>>(w_qkv, w_attn_out, w_mlp1, w_mlp2);

    ada_kernel<<<(6 * DIM + 255) / 256, 256>>>(c, w_ada, b_ada);
    ln_mod_kernel<<<BS, 256>>>(x, w_ln1, 0, 1, p_h);

    tgemm_kernel<<<dim3(3 * DIM / 128, BS / 128), 256, GSMEM>>>(
        p_h, p_wh + WO_QKV, nullptr, nullptr, p_qkv, BS, 3 * DIM, DIM, 0, 0, 1);

    rope_kernel<<<(BATCH * SEQ * NH * 32 + 255) / 256, 256>>>(cosb, sinb);

    flash_kernel<<<dim3(SEQ / 64, BATCH * NH), 128>>>();

    tgemm_kernel<<<dim3(DIM / 128, BS / 128), 256, GSMEM>>>(
        p_o, p_wh + WO_ATTN, nullptr, x, p_x2, BS, DIM, DIM, 0, 2, 0);

    ln_mod_kernel<<<BS, 256>>>(p_x2, w_ln2, 3, 4, p_h);

    tgemm_kernel<<<dim3(MLP_HID / 128, BS / 128), 256, GSMEM>>>(
        p_h, p_wh + WO_MLP1, b_mlp1, nullptr, p_mid, BS, MLP_HID, DIM, 1, 0, 1);

    tgemm_kernel<<<dim3(DIM / 128, BS / 128), 256, GSMEM>>>(
        p_mid, p_wh + WO_MLP2, b_mlp2, p_x2, out, BS, DIM, MLP_HID, 0, 5, 0);
}

// round 9
// speedup vs baseline: 5.6862x; 1.0038x over previous
#include <cuda_runtime.h>
#include <cuda_fp16.h>
#include <math.h>
#include <stdint.h>

#define DIM 1024
#define NH 16
#define HD 64
#define BATCH 4
#define SEQ 1024
#define BS (BATCH*SEQ)
#define MLP_HID 4096
#define LN_EPS 1e-5f

// ---------------- scratch ----------------
__device__ float  g_mod[BATCH * 6 * DIM];
__device__ __half g_h[BS * DIM];
__device__ __half g_qkv[BS * 3 * DIM];
__device__ __half g_o[BS * DIM];
__device__ float  g_x2[BS * DIM];
__device__ __half g_mid[BS * MLP_HID];
#define WO_QKV  0
#define WO_ATTN (3*DIM*DIM)
#define WO_MLP1 (WO_ATTN + DIM*DIM)
#define WO_MLP2 (WO_MLP1 + DIM*MLP_HID)
#define W_TOTAL (WO_MLP2 + MLP_HID*DIM)
__device__ __half g_wh[W_TOTAL];

// ================= helpers =================
__device__ __forceinline__ void mma16(float* c, const uint32_t* a, const uint32_t* b) {
    asm volatile(
        "mma.sync.aligned.m16n8k16.row.col.f32.f16.f16.f32 "
        "{%0,%1,%2,%3}, {%4,%5,%6,%7}, {%8,%9}, {%0,%1,%2,%3};"
        : "+f"(c[0]), "+f"(c[1]), "+f"(c[2]), "+f"(c[3])
        : "r"(a[0]), "r"(a[1]), "r"(a[2]), "r"(a[3]), "r"(b[0]), "r"(b[1]));
}
__device__ __forceinline__ void ldsm4(uint32_t* r, uint32_t addr) {
    asm volatile("ldmatrix.sync.aligned.m8n8.x4.shared.b16 {%0,%1,%2,%3}, [%4];"
        : "=r"(r[0]), "=r"(r[1]), "=r"(r[2]), "=r"(r[3]) : "r"(addr));
}
__device__ __forceinline__ void ldsm4t(uint32_t* r, uint32_t addr) {
    asm volatile("ldmatrix.sync.aligned.m8n8.x4.trans.shared.b16 {%0,%1,%2,%3}, [%4];"
        : "=r"(r[0]), "=r"(r[1]), "=r"(r[2]), "=r"(r[3]) : "r"(addr));
}
__device__ __forceinline__ void ldsm2t(uint32_t* r, uint32_t addr) {
    asm volatile("ldmatrix.sync.aligned.m8n8.x2.trans.shared.b16 {%0,%1}, [%2];"
        : "=r"(r[0]), "=r"(r[1]) : "r"(addr));
}
__device__ __forceinline__ uint32_t packh2(float a, float b) {
    __half2 h = __floats2half2_rn(a, b);
    return *(uint32_t*)&h;
}
__device__ __forceinline__ float gelu_f(float u) {
    float y = 0.7978845608028654f * (u + 0.044715f * u * u * u);
    float e = __expf(2.0f * y);
    return u * (1.0f - __fdividef(1.0f, e + 1.0f));
}

#define CP16(smem, gmem) \
    asm volatile("cp.async.cg.shared.global [%0], [%1], 16;" :: "r"(smem), "l"(gmem))
#define CP_COMMIT() asm volatile("cp.async.commit_group;" ::: "memory")
#define CP_WAIT1()  asm volatile("cp.async.wait_group 1;" ::: "memory")

// ---------------- all weights fp32 -> fp16, one launch ----------------
__global__ void cvt_all_kernel(const float* __restrict__ wqkv,
                               const float* __restrict__ wattn,
                               const float* __restrict__ wmlp1,
                               const float* __restrict__ wmlp2)
{
    int i = (blockIdx.x * blockDim.x + threadIdx.x) * 8;
    if (i >= W_TOTAL) return;
    const float* src;
    int off;
    if (i < WO_ATTN)      { src = wqkv;  off = i; }
    else if (i < WO_MLP1) { src = wattn; off = i - WO_ATTN; }
    else if (i < WO_MLP2) { src = wmlp1; off = i - WO_MLP1; }
    else                  { src = wmlp2; off = i - WO_MLP2; }
    float4 v0 = *(const float4*)(src + off);
    float4 v1 = *(const float4*)(src + off + 4);
    uint4 u;
    u.x = packh2(v0.x, v0.y); u.y = packh2(v0.z, v0.w);
    u.z = packh2(v1.x, v1.y); u.w = packh2(v1.z, v1.w);
    *(uint4*)(g_wh + i) = u;
}

// ============ fp16 mma GEMM, BK=64, 2-stage cp.async, 2 CTA/SM ============
#define PADA 72
#define PADB 136
#define ASZH (128 * PADA)
#define BSZH (64 * PADB)
#define STGB ((ASZH + BSZH) * 2)
#define NSTAGE 2
#define GSMEM (NSTAGE * STGB)

__global__ void __launch_bounds__(256, 2)
tgemm_kernel(const __half* __restrict__ A,
             const __half* __restrict__ B,
             const float* __restrict__ bias,
             const float* __restrict__ resid,
             void* __restrict__ C,
             int M, int N, int K, int act, int gate_chunk, int out_half)
{
    extern __shared__ char fsraw[];
    const uint32_t smb = (uint32_t)__cvta_generic_to_shared(fsraw);

    const int t = threadIdx.x, lane = t & 31, wid = t >> 5;
    const int warpM = wid >> 2, warpN = wid & 3;
    const int bm = blockIdx.y * 128, bn = blockIdx.x * 128;
    const int gid = lane >> 2, tig = lane & 3;

    const int am = (t * 8) >> 6;
    const int ak = (t * 8) & 63;
    const int bk = (t * 8) >> 7;
    const int bnn = (t * 8) & 127;

    float acc[4][4][4];
    #pragma unroll
    for (int i = 0; i < 4; i++)
        #pragma unroll
        for (int j = 0; j < 4; j++)
            #pragma unroll
            for (int q = 0; q < 4; q++) acc[i][j][q] = 0.f;

    const int NC = K >> 6;

    auto issue = [&](int stage, int kc) {
        uint32_t abase = smb + (uint32_t)(stage * STGB);
        uint32_t bbase = abase + (uint32_t)(ASZH * 2);
        #pragma unroll
        for (int i = 0; i < 4; i++) {
            int m = am + i * 32;
            CP16(abase + (uint32_t)(m * PADA + ak) * 2u,
                 A + (size_t)(bm + m) * K + kc * 64 + ak);
        }
        #pragma unroll
        for (int i = 0; i < 4; i++) {
            int kk = bk + i * 16;
            CP16(bbase + (uint32_t)(kk * PADB + bnn) * 2u,
                 B + (size_t)(kc * 64 + kk) * N + bn + bnn);
        }
    };

    issue(0, 0); CP_COMMIT();
    if (NC > 1) issue(1, 1);
    CP_COMMIT();

    const int arow = warpM * 64 + (lane & 15);
    const int akof = (lane >> 4) * 8;
    const int bkl = lane & 15;
    const int bgof = (lane >> 4) * 8;

    for (int kc = 0; kc < NC; kc++) {
        CP_WAIT1();
        __syncthreads();

        const uint32_t sA = smb + (uint32_t)((kc & 1) * STGB);
        const uint32_t sB = sA + (uint32_t)(ASZH * 2);

        #pragma unroll
        for (int ks = 0; ks < 4; ks++) {
            uint32_t af[4][4], bf[2][4];
            #pragma unroll
            for (int mi = 0; mi < 4; mi++) {
                int row = arow + mi * 16;
                ldsm4(af[mi], sA + (uint32_t)(row * PADA + ks * 16 + akof) * 2u);
            }
            #pragma unroll
            for (int g = 0; g < 2; g++) {
                int n0 = warpN * 32 + g * 16 + bgof;
                int k = ks * 16 + bkl;
                ldsm4t(bf[g], sB + (uint32_t)(k * PADB + n0) * 2u);
            }
            #pragma unroll
            for (int mi = 0; mi < 4; mi++)
                #pragma unroll
                for (int ni = 0; ni < 4; ni++)
                    mma16(acc[mi][ni], af[mi], &bf[ni >> 1][(ni & 1) * 2]);
        }

        if (kc + 2 < NC) {
            __syncthreads();
            issue(kc & 1, kc + 2);
        }
        CP_COMMIT();
    }

    // ---- epilogue ----
    #pragma unroll
    for (int mi = 0; mi < 4; mi++) {
        #pragma unroll
        for (int ni = 0; ni < 4; ni++) {
            int r0 = bm + warpM * 64 + mi * 16 + gid;
            int c0 = bn + warpN * 32 + ni * 8 + tig * 2;
            float v0 = acc[mi][ni][0], v1 = acc[mi][ni][1];
            float v2 = acc[mi][ni][2], v3 = acc[mi][ni][3];
            if (bias) {
                float b0 = bias[c0], b1 = bias[c0 + 1];
                v0 += b0; v1 += b1; v2 += b0; v3 += b1;
            }
            if (act) {
                v0 = gelu_f(v0); v1 = gelu_f(v1);
                v2 = gelu_f(v2); v3 = gelu_f(v3);
            }
            if (resid) {
                const float* gp0 = g_mod + (r0 >> 10) * 6 * DIM + gate_chunk * DIM + c0;
                const float* gp1 = g_mod + ((r0 + 8) >> 10) * 6 * DIM + gate_chunk * DIM + c0;
                float2 rr0 = *(const float2*)(resid + (size_t)r0 * N + c0);
                float2 rr1 = *(const float2*)(resid + (size_t)(r0 + 8) * N + c0);
                v0 = rr0.x + gp0[0] * v0;
                v1 = rr0.y + gp0[1] * v1;
                v2 = rr1.x + gp1[0] * v2;
                v3 = rr1.y + gp1[1] * v3;
            }
            if (out_half) {
                __half* Ch = (__half*)C;
                *(uint32_t*)(Ch + (size_t)r0 * N + c0)       = packh2(v0, v1);
                *(uint32_t*)(Ch + (size_t)(r0 + 8) * N + c0) = packh2(v2, v3);
            } else {
                float* Cf = (float*)C;
                *(float2*)(Cf + (size_t)r0 * N + c0)       = make_float2(v0, v1);
                *(float2*)(Cf + (size_t)(r0 + 8) * N + c0) = make_float2(v2, v3);
            }
        }
    }
}

// ============ fused flash attention: cp.async 3-buffer K/V ring ============
#define FP 72
#define KVT (64 * FP)          // halves per tile
__global__ void __launch_bounds__(128)
flash_kernel()
{
    __shared__ __align__(16) __half Qs[KVT];
    __shared__ __align__(16) __half Ks[3][KVT];
    __shared__ __align__(16) __half Vs[3][KVT];

    const int t = threadIdx.x, lane = t & 31, wid = t >> 5;
    const int gid = lane >> 2, tig = lane & 3;
    const int bh = blockIdx.y, b = bh >> 4, h = bh & 15;
    const int q0 = blockIdx.x * 64;
    const int row = wid * 16 + gid;

    // fill indices for K/V cp.async: 4 chunks of 16B per thread per tile
    const int fr = (t * 8) >> 6;      // row for i=0 (advance 16 per i)
    const int fc = (t * 8) & 63;      // col (halves)

    auto issue_kv = [&](int buf, int kt) {
        uint32_t kb = (uint32_t)__cvta_generic_to_shared(&Ks[buf][0]);
        uint32_t vbuf = (uint32_t)__cvta_generic_to_shared(&Vs[buf][0]);
        #pragma unroll
        for (int i = 0; i < 4; i++) {
            int r = fr + i * 16;
            const __half* kg = g_qkv + ((size_t)(b * SEQ + kt + r) * 3 + 1) * 1024 + h * 64 + fc;
            const __half* vg = g_qkv + ((size_t)(b * SEQ + kt + r) * 3 + 2) * 1024 + h * 64 + fc;
            CP16(kb   + (uint32_t)(r * FP + fc) * 2u, kg);
            CP16(vbuf + (uint32_t)(r * FP + fc) * 2u, vg);
        }
    };

    // load Q tile (sync, once)
    #pragma unroll
    for (int i = 0; i < 4; i++) {
        int e = (i * 128 + t) * 8;
        int r = e >> 6, c = e & 63;
        *(uint4*)&Qs[r * FP + c] =
            *(const uint4*)(g_qkv + ((size_t)(b * SEQ + q0 + r) * 3) * 1024 + h * 64 + c);
    }

    issue_kv(0, 0); CP_COMMIT();
    issue_kv(1, 64); CP_COMMIT();

    float m_i[2] = { -1e30f, -1e30f };
    float l_i[2] = { 0.f, 0.f };
    float oacc[8][4];
    #pragma unroll
    for (int ni = 0; ni < 8; ni++)
        #pragma unroll
        for (int q = 0; q < 4; q++) oacc[ni][q] = 0.f;

    for (int it = 0; it < SEQ / 64; it++) {
        CP_WAIT1();
        __syncthreads();          // tile `it` visible; all warps done with tile it-1

        if (it + 2 < SEQ / 64) issue_kv((it + 2) % 3, (it + 2) * 64);
        CP_COMMIT();

        const __half* Kc = Ks[it % 3];
        const uint32_t vb = (uint32_t)__cvta_generic_to_shared(&Vs[it % 3][0]);

        float sacc[8][4];
        #pragma unroll
        for (int ni = 0; ni < 8; ni++)
            #pragma unroll
            for (int q = 0; q < 4; q++) sacc[ni][q] = 0.f;

        #pragma unroll
        for (int ks = 0; ks < 4; ks++) {
            uint32_t af[4];
            af[0] = *(uint32_t*)&Qs[row * FP + ks * 16 + 2 * tig];
            af[1] = *(uint32_t*)&Qs[(row + 8) * FP + ks * 16 + 2 * tig];
            af[2] = *(uint32_t*)&Qs[row * FP + ks * 16 + 8 + 2 * tig];
            af[3] = *(uint32_t*)&Qs[(row + 8) * FP + ks * 16 + 8 + 2 * tig];
            #pragma unroll
            for (int ni = 0; ni < 8; ni++) {
                int n = ni * 8 + gid;
                uint32_t bf[2];
                bf[0] = *(const uint32_t*)&Kc[n * FP + ks * 16 + 2 * tig];
                bf[1] = *(const uint32_t*)&Kc[n * FP + ks * 16 + 8 + 2 * tig];
                mma16(sacc[ni], af, bf);
            }
        }

        #pragma unroll
        for (int ni = 0; ni < 8; ni++)
            #pragma unroll
            for (int q = 0; q < 4; q++) sacc[ni][q] *= 0.125f;

        float rmax[2] = { -1e30f, -1e30f };
        #pragma unroll
        for (int ni = 0; ni < 8; ni++) {
            rmax[0] = fmaxf(rmax[0], fmaxf(sacc[ni][0], sacc[ni][1]));
            rmax[1] = fmaxf(rmax[1], fmaxf(sacc[ni][2], sacc[ni][3]));
        }
        #pragma unroll
        for (int w = 1; w <= 2; w <<= 1) {
            rmax[0] = fmaxf(rmax[0], __shfl_xor_sync(0xffffffff, rmax[0], w));
            rmax[1] = fmaxf(rmax[1], __shfl_xor_sync(0xffffffff, rmax[1], w));
        }
        float mnew0 = fmaxf(m_i[0], rmax[0]);
        float mnew1 = fmaxf(m_i[1], rmax[1]);
        float alpha0 = __expf(m_i[0] - mnew0);
        float alpha1 = __expf(m_i[1] - mnew1);
        m_i[0] = mnew0; m_i[1] = mnew1;

        float rsum[2] = { 0.f, 0.f };
        #pragma unroll
        for (int ni = 0; ni < 8; ni++) {
            sacc[ni][0] = __expf(sacc[ni][0] - mnew0);
            sacc[ni][1] = __expf(sacc[ni][1] - mnew0);
            sacc[ni][2] = __expf(sacc[ni][2] - mnew1);
            sacc[ni][3] = __expf(sacc[ni][3] - mnew1);
            rsum[0] += sacc[ni][0] + sacc[ni][1];
            rsum[1] += sacc[ni][2] + sacc[ni][3];
        }
        #pragma unroll
        for (int w = 1; w <= 2; w <<= 1) {
            rsum[0] += __shfl_xor_sync(0xffffffff, rsum[0], w);
            rsum[1] += __shfl_xor_sync(0xffffffff, rsum[1], w);
        }
        l_i[0] = l_i[0] * alpha0 + rsum[0];
        l_i[1] = l_i[1] * alpha1 + rsum[1];

        #pragma unroll
        for (int ni = 0; ni < 8; ni++) {
            oacc[ni][0] *= alpha0; oacc[ni][1] *= alpha0;
            oacc[ni][2] *= alpha1; oacc[ni][3] *= alpha1;
        }

        #pragma unroll
        for (int ks = 0; ks < 4; ks++) {
            uint32_t af[4];
            af[0] = packh2(sacc[2*ks][0],   sacc[2*ks][1]);
            af[1] = packh2(sacc[2*ks][2],   sacc[2*ks][3]);
            af[2] = packh2(sacc[2*ks+1][0], sacc[2*ks+1][1]);
            af[3] = packh2(sacc[2*ks+1][2], sacc[2*ks+1][3]);
            int k = ks * 16 + (lane & 15);
            #pragma unroll
            for (int ni = 0; ni < 8; ni++) {
                uint32_t bf[2];
                ldsm2t(bf, vb + (uint32_t)(k * FP + ni * 8) * 2u);
                mma16(oacc[ni], af, bf);
            }
        }
        // no trailing barrier: next-iter barrier protects buffer reuse
    }

    float inv0 = __fdividef(1.0f, l_i[0]);
    float inv1 = __fdividef(1.0f, l_i[1]);
    #pragma unroll
    for (int ni = 0; ni < 8; ni++) {
        int c = h * 64 + ni * 8 + tig * 2;
        __half* op0 = g_o + (size_t)(b * SEQ + q0 + row) * 1024 + c;
        __half* op1 = g_o + (size_t)(b * SEQ + q0 + row + 8) * 1024 + c;
        *(uint32_t*)op0 = packh2(oacc[ni][0] * inv0, oacc[ni][1] * inv0);
        *(uint32_t*)op1 = packh2(oacc[ni][2] * inv1, oacc[ni][3] * inv1);
    }
}

// ---------------- adaLN modulation ----------------
__global__ void ada_kernel(const float* __restrict__ c,
                           const float* __restrict__ w_ada,
                           const float* __restrict__ b_ada)
{
    int j = blockIdx.x * blockDim.x + threadIdx.x;
    if (j >= 6 * DIM) return;
    float s0 = b_ada[j], s1 = s0, s2 = s0, s3 = s0;
    for (int k = 0; k < DIM; k++) {
        float w = w_ada[k * (6 * DIM) + j];
        s0 += c[k] * w;
        s1 += c[DIM + k] * w;
        s2 += c[2 * DIM + k] * w;
        s3 += c[3 * DIM + k] * w;
    }
    g_mod[j] = s0;
    g_mod[6 * DIM + j] = s1;
    g_mod[12 * DIM + j] = s2;
    g_mod[18 * DIM + j] = s3;
}

// ---------------- LayerNorm + modulate -> half ----------------
__global__ void ln_mod_kernel(const float* __restrict__ x,
                              const float* __restrict__ w,
                              int shift_chunk, int scale_chunk,
                              __half* __restrict__ out)
{
    int row = blockIdx.x;
    int b = row >> 10;
    int t = threadIdx.x;
    const float* xr = x + (size_t)row * DIM;
    float4 v = *(const float4*)(xr + t * 4);
    float sum = v.x + v.y + v.z + v.w;
    float sq  = v.x*v.x + v.y*v.y + v.z*v.z + v.w*v.w;

    __shared__ float s1[256], s2[256];
    s1[t] = sum; s2[t] = sq;
    __syncthreads();
    for (int off = 128; off > 0; off >>= 1) {
        if (t < off) { s1[t] += s1[t + off]; s2[t] += s2[t + off]; }
        __syncthreads();
    }
    float mean = s1[0] * (1.0f / DIM);
    float var  = s2[0] * (1.0f / DIM) - mean * mean;
    float rstd = rsqrtf(var + LN_EPS);

    const float* shiftp = g_mod + b * 6 * DIM + shift_chunk * DIM;
    const float* scalep = g_mod + b * 6 * DIM + scale_chunk * DIM;
    __half* orow = out + (size_t)row * DIM;
    float y[4];
    #pragma unroll
    for (int u = 0; u < 4; u++) {
        int col = t * 4 + u;
        float xv = (u == 0) ? v.x : (u == 1) ? v.y : (u == 2) ? v.z : v.w;
        float yy = (xv - mean) * rstd * w[col];
        y[u] = yy * (1.0f + scalep[col]) + shiftp[col];
    }
    uint2 pk;
    pk.x = packh2(y[0], y[1]);
    pk.y = packh2(y[2], y[3]);
    *(uint2*)(orow + t * 4) = pk;
}

// ---------------- RoPE (half in/out) ----------------
__global__ void rope_kernel(const float* __restrict__ cosb,
                            const float* __restrict__ sinb)
{
    int idx = blockIdx.x * blockDim.x + threadIdx.x;
    if (idx >= BATCH * SEQ * NH * 32) return;
    int i = idx & 31;
    int h = (idx >> 5) & 15;
    int s = (idx >> 9) & 1023;
    int b = idx >> 19;
    float co = cosb[s * 32 + i];
    float si = sinb[s * 32 + i];
    #pragma unroll
    for (int p = 0; p < 2; p++) {
        size_t base = ((((size_t)(b * SEQ + s)) * 3 + p) * NH + h) * HD;
        float t1 = __half2float(g_qkv[base + i]);
        float t2 = __half2float(g_qkv[base + 32 + i]);
        g_qkv[base + i]      = __float2half_rn(t1 * co - t2 * si);
        g_qkv[base + 32 + i] = __float2half_rn(t2 * co + t1 * si);
    }
}

// ---------------- launch ----------------
extern "C" void kernel_launch(void* const* d_in, const int* in_sizes, int n_in,
                              void* d_out, int out_size)
{
    const float* x          = (const float*)d_in[0];
    const float* cosb       = (const float*)d_in[1];
    const float* sinb       = (const float*)d_in[2];
    const float* c          = (const float*)d_in[3];
    const float* w_ln1      = (const float*)d_in[4];
    const float* w_ln2      = (const float*)d_in[5];
    const float* w_qkv      = (const float*)d_in[6];
    const float* w_attn_out = (const float*)d_in[7];
    const float* w_mlp1     = (const float*)d_in[8];
    const float* b_mlp1     = (const float*)d_in[9];
    const float* w_mlp2     = (const float*)d_in[10];
    const float* b_mlp2     = (const float*)d_in[11];
    const float* w_ada      = (const float*)d_in[12];
    const float* b_ada      = (const float*)d_in[13];
    float* out = (float*)d_out;

    __half *p_h, *p_qkv, *p_o, *p_mid, *p_wh;
    float *p_x2;
    cudaGetSymbolAddress((void**)&p_h,   g_h);
    cudaGetSymbolAddress((void**)&p_qkv, g_qkv);
    cudaGetSymbolAddress((void**)&p_o,   g_o);
    cudaGetSymbolAddress((void**)&p_x2,  g_x2);
    cudaGetSymbolAddress((void**)&p_mid, g_mid);
    cudaGetSymbolAddress((void**)&p_wh,  g_wh);

    cudaFuncSetAttribute(tgemm_kernel,
                         cudaFuncAttributeMaxDynamicSharedMemorySize, GSMEM);

    cvt_all_kernel<<<(W_TOTAL/8 + 255)/256, 256>>>(w_qkv, w_attn_out, w_mlp1, w_mlp2);

    ada_kernel<<<(6 * DIM + 255) / 256, 256>>>(c, w_ada, b_ada);
    ln_mod_kernel<<<BS, 256>>>(x, w_ln1, 0, 1, p_h);

    tgemm_kernel<<<dim3(3 * DIM / 128, BS / 128), 256, GSMEM>>>(
        p_h, p_wh + WO_QKV, nullptr, nullptr, p_qkv, BS, 3 * DIM, DIM, 0, 0, 1);

    rope_kernel<<<(BATCH * SEQ * NH * 32 + 255) / 256, 256>>>(cosb, sinb);

    flash_kernel<<<dim3(SEQ / 64, BATCH * NH), 128>>>();

    tgemm_kernel<<<dim3(DIM / 128, BS / 128), 256, GSMEM>>>(
        p_o, p_wh + WO_ATTN, nullptr, x, p_x2, BS, DIM, DIM, 0, 2, 0);

    ln_mod_kernel<<<BS, 256>>>(p_x2, w_ln2, 3, 4, p_h);

    tgemm_kernel<<<dim3(MLP_HID / 128, BS / 128), 256, GSMEM>>>(
        p_h, p_wh + WO_MLP1, b_mlp1, nullptr, p_mid, BS, MLP_HID, DIM, 1, 0, 1);

    tgemm_kernel<<<dim3(DIM / 128, BS / 128), 256, GSMEM>>>(
        p_mid, p_wh + WO_MLP2, b_mlp2, p_x2, out, BS, DIM, MLP_HID, 0, 5, 0);
}